// round 10
// baseline (speedup 1.0000x reference)
#include <cuda_runtime.h>
#include <math.h>
#include <stdint.h>

#define SEQ   512
#define HID   512
#define IN0   1088
#define IN1   1024
#define GATES 2048
#define MLPH  100
#define PAIRD 2048
#define RCTAS 64   // CTAs per LSTM direction
#define WIN   1.5f

// ---------------- device scratch (no allocations allowed) ----------------
__device__ float g_x0[SEQ * IN0];
__device__ float g_xw0[SEQ * GATES];
__device__ float g_xw1[SEQ * GATES];
__device__ float g_h0[SEQ * 2 * HID];
__device__ float g_h1[SEQ * 2 * HID];
__device__ float g_sh[SEQ * MLPH];
__device__ float g_sm[SEQ * MLPH];
__device__ float g_scores[SEQ * SEQ];
// self-validating h exchange: [dir][buffer=t&1][granule 0..255] (8B = 2 h values)
__device__ __align__(128) unsigned long long g_hx[2][2][256];
__device__ __align__(128) unsigned g_cnt[2][32];    // one-time start barrier
__device__ __align__(128) unsigned g_exit[2][32];   // exit/reset barrier

// ---------------- helpers ----------------
__device__ __forceinline__ unsigned ld_acq(const unsigned* p) {
    unsigned v;
    asm volatile("ld.acquire.gpu.u32 %0, [%1];" : "=r"(v) : "l"(p) : "memory");
    return v;
}
__device__ __forceinline__ unsigned long long ld_rlx64(const unsigned long long* p) {
    unsigned long long v;
    asm volatile("ld.relaxed.gpu.global.b64 %0, [%1];" : "=l"(v) : "l"(p) : "memory");
    return v;
}
__device__ __forceinline__ void st_rlx64(unsigned long long* p, unsigned long long v) {
    asm volatile("st.relaxed.gpu.global.b64 [%0], %1;" :: "l"(p), "l"(v) : "memory");
}
__device__ __forceinline__ float tanhap(float x) {             // HW tanh
    float y;
    asm("tanh.approx.f32 %0, %1;" : "=f"(y) : "f"(x));
    return y;
}
__device__ __forceinline__ float sigap(float x) {              // sigmoid via HW tanh
    return fmaf(0.5f, tanhap(0.5f * x), 0.5f);
}

// ---------------- embeddings ----------------
__global__ void embed_kernel(const int* __restrict__ wi, const int* __restrict__ pi,
                             const float* __restrict__ we, const float* __restrict__ pe) {
    int t = blockIdx.x;
    int w = wi[t], p = pi[t];
    const float* wr = we + (size_t)w * 1024;
    const float* pr = pe + (size_t)p * 64;
    float* out = g_x0 + (size_t)t * IN0;
    for (int i = threadIdx.x; i < 1024; i += blockDim.x) out[i] = wr[i];
    for (int i = threadIdx.x; i < 64; i += blockDim.x) out[1024 + i] = pr[i];
}

// ---- dual GEMM: z selects (B, bias, C); C[M,N] = A[M,K] * B[N,K]^T (+bias) ----
// BM=128, BN=128, BK=16, 256 threads, 8x8 register tile (L1-traffic per FMA halved
// vs the 4x4/64x64 version that was L1-bound at 76.8%).
__global__ void __launch_bounds__(256, 1)
gemm_dual(const float* __restrict__ A, int lda,
          const float* __restrict__ B0, const float* __restrict__ B1, int ldb,
          const float* __restrict__ bias0, const float* __restrict__ bias1,
          float* __restrict__ C0, float* __restrict__ C1, int ldc,
          int M, int N, int K) {
    const float* B = blockIdx.z ? B1 : B0;
    const float* bias = blockIdx.z ? bias1 : bias0;
    float* C = blockIdx.z ? C1 : C0;

    __shared__ __align__(16) float As[16][132];
    __shared__ __align__(16) float Bs[16][132];
    int bm = blockIdx.y * 128, bn = blockIdx.x * 128;
    int tid = threadIdx.x;
    int tx = tid & 15, ty = tid >> 4;          // 16 x 16 thread grid
    int lr = tid >> 1;                         // 0..127: row within tile
    int lk = (tid & 1) * 8;                    // 0 or 8: k-offset (8 floats = 2 float4)

    float acc[8][8];
#pragma unroll
    for (int i = 0; i < 8; i++)
#pragma unroll
        for (int j = 0; j < 8; j++) acc[i][j] = 0.f;

    int rowa = bm + lr;
    int rowb = bn + lr;
    bool va_ok = rowa < M;
    bool vb_ok = rowb < N;

    // preload tile 0 (2 float4 each for A and B)
    float4 va0 = make_float4(0.f, 0.f, 0.f, 0.f), va1 = va0, vb0 = va0, vb1 = va0;
    if (va_ok) {
        const float* p = A + (size_t)rowa * lda + lk;
        va0 = *(const float4*)p; va1 = *(const float4*)(p + 4);
    }
    if (vb_ok) {
        const float* p = B + (size_t)rowb * ldb + lk;
        vb0 = *(const float4*)p; vb1 = *(const float4*)(p + 4);
    }

    for (int k0 = 0; k0 < K; k0 += 16) {
        As[lk + 0][lr] = va0.x; As[lk + 1][lr] = va0.y; As[lk + 2][lr] = va0.z; As[lk + 3][lr] = va0.w;
        As[lk + 4][lr] = va1.x; As[lk + 5][lr] = va1.y; As[lk + 6][lr] = va1.z; As[lk + 7][lr] = va1.w;
        Bs[lk + 0][lr] = vb0.x; Bs[lk + 1][lr] = vb0.y; Bs[lk + 2][lr] = vb0.z; Bs[lk + 3][lr] = vb0.w;
        Bs[lk + 4][lr] = vb1.x; Bs[lk + 5][lr] = vb1.y; Bs[lk + 6][lr] = vb1.z; Bs[lk + 7][lr] = vb1.w;
        __syncthreads();
        // prefetch next tile while computing
        if (k0 + 16 < K) {
            if (va_ok) {
                const float* p = A + (size_t)rowa * lda + k0 + 16 + lk;
                va0 = *(const float4*)p; va1 = *(const float4*)(p + 4);
            }
            if (vb_ok) {
                const float* p = B + (size_t)rowb * ldb + k0 + 16 + lk;
                vb0 = *(const float4*)p; vb1 = *(const float4*)(p + 4);
            }
        }
#pragma unroll
        for (int k = 0; k < 16; k++) {
            float a[8], b[8];
            *(float4*)&a[0] = *(const float4*)&As[k][ty * 8];
            *(float4*)&a[4] = *(const float4*)&As[k][ty * 8 + 4];
            *(float4*)&b[0] = *(const float4*)&Bs[k][tx * 8];
            *(float4*)&b[4] = *(const float4*)&Bs[k][tx * 8 + 4];
#pragma unroll
            for (int i = 0; i < 8; i++)
#pragma unroll
                for (int j = 0; j < 8; j++) acc[i][j] = fmaf(a[i], b[j], acc[i][j]);
        }
        __syncthreads();
    }
#pragma unroll
    for (int i = 0; i < 8; i++) {
        int r = bm + ty * 8 + i;
        if (r >= M) continue;
#pragma unroll
        for (int j = 0; j < 8; j++) {
            int c = bn + tx * 8 + j;
            if (c < N) C[(size_t)r * ldc + c] = acc[i][j] + (bias ? bias[c] : 0.f);
        }
    }
}

// ---------------- LSTM recurrence: register weights + self-validating h exchange --------
// (R7-winning structure — DO NOT restructure; two rewrites have regressed)
// grid = 128 CTAs (64 fwd, 64 bwd), 256 threads. CTA owns 8 h-indices (32 gate rows).
// h published as v = h + 4*(t mod 7), double-buffered by t&1; value IS the sync.
__global__ void __launch_bounds__(256, 1)
lstm_layer(const float* __restrict__ whh_f, const float* __restrict__ whh_b,
           const float* __restrict__ xw_f, const float* __restrict__ xw_b,
           float* __restrict__ hout) {
    __shared__ float sh[512];
    __shared__ float zp[32 * 9];
    __shared__ float sact[32];

    int dir = blockIdx.x >> 6;
    int j = blockIdx.x & 63;
    int hbase = j * 8;
    const float* W = dir ? whh_b : whh_f;
    const float* xw = dir ? xw_b : xw_f;
    int tid = threadIdx.x;

    int row = tid & 31;            // gate row within CTA (0..31)
    int ck = tid >> 5;             // K chunk (0..7)
    const int base = ck * 64;

    // weights into registers
    float w[64];
    {
        const float* src = W + (size_t)((row >> 3) * 512 + hbase + (row & 7)) * 512 + base;
#pragma unroll
        for (int i = 0; i < 64; i += 4) {
            float4 v = *(const float4*)(src + i);
            w[i] = v.x; w[i + 1] = v.y; w[i + 2] = v.z; w[i + 3] = v.w;
        }
    }

    // one-time: poison own hx granules, then grid start-barrier (per direction)
    if (tid == 0) {
        unsigned long long poison =
            ((unsigned long long)__float_as_uint(1e30f) << 32) | __float_as_uint(1e30f);
#pragma unroll
        for (int b = 0; b < 2; b++)
#pragma unroll
            for (int q = 0; q < 4; q++)
                st_rlx64(&g_hx[dir][b][j * 4 + q], poison);
        __threadfence();
        atomicAdd(&g_cnt[dir][0], 1u);
        while (ld_acq(&g_cnt[dir][0]) < (unsigned)RCTAS) { }
    }
    __syncthreads();

    float c_state = 0.f;           // owned by threads 0..7
    int kp = 0, kc = 0;            // t mod 7 (producer), (t-1) mod 7 (consumer)

    for (int t = 0; t < 512; t++) {
        int pos = dir ? (511 - t) : t;
        float coffp = 4.0f * (float)kp;
        float coffc = 4.0f * (float)kc;

        // prefetch gate inputs (independent of h) — overlaps the poll below
        float xg = 0.f;
        if (tid < 32) {
            const float* xr = xw + (size_t)pos * GATES + (tid >> 3) * 512 + hbase + (tid & 7);
            xg = __ldg(xr);
        }

        // gather h_prev: every thread polls ONE self-validating 8B granule
        if (t == 0) {
            ((float2*)sh)[tid] = make_float2(0.f, 0.f);
        } else {
            const unsigned long long* src = &g_hx[dir][(t - 1) & 1][tid];
            float lo, hi;
            for (;;) {
                unsigned long long v = ld_rlx64(src);
                lo = __uint_as_float((unsigned)v);
                hi = __uint_as_float((unsigned)(v >> 32));
                if (fabsf(lo - coffc) <= WIN && fabsf(hi - coffc) <= WIN) break;
            }
            ((float2*)sh)[tid] = make_float2(lo - coffc, hi - coffc);
        }
        __syncthreads();   // sh ready

        // matvec partial: register weights x broadcast smem h
        {
            const float* hv = sh + base;
            float a0 = 0.f, a1 = 0.f, a2 = 0.f, a3 = 0.f;
#pragma unroll
            for (int i = 0; i < 64; i += 4) {
                float4 h4 = *(const float4*)(hv + i);
                a0 = fmaf(w[i + 0], h4.x, a0);
                a1 = fmaf(w[i + 1], h4.y, a1);
                a2 = fmaf(w[i + 2], h4.z, a2);
                a3 = fmaf(w[i + 3], h4.w, a3);
            }
            zp[row * 9 + ck] = (a0 + a1) + (a2 + a3);
        }
        __syncthreads();   // zp ready

        // warp 0: gate-row sums + activations; 8 owners update state + publish
        if (tid < 32) {
            const float* zr = zp + tid * 9;
            float z = xg;
#pragma unroll
            for (int c = 0; c < 8; c++) z += zr[c];
            sact[tid] = ((tid >> 3) == 2) ? tanhap(z) : sigap(z);
        }
        __syncwarp();
        if (tid < 8) {
            float gi = sact[tid];
            float gf = sact[8 + tid];
            float gg = sact[16 + tid];
            float go_ = sact[24 + tid];
            c_state = gf * c_state + gi * gg;
            float h = go_ * tanhap(c_state);
            __stcg(hout + (size_t)pos * 1024 + (dir << 9) + hbase + tid, h);
            // publish: v = h + 4*(t%7), packed 2-per-b64, fire-and-forget
            float vv = h + coffp;
            float partner = __shfl_xor_sync(0x000000FFu, vv, 1);
            if ((tid & 1) == 0) {
                unsigned long long pk =
                    ((unsigned long long)__float_as_uint(partner) << 32) | __float_as_uint(vv);
                st_rlx64(&g_hx[dir][t & 1][j * 4 + (tid >> 1)], pk);
            }
        }
        kc = kp;
        kp = (kp == 6) ? 0 : kp + 1;
    }

    // exit/reset: make counters zero for the next launch / graph replay
    __syncthreads();
    if (tid == 0) {
        __threadfence();
        atomicAdd(&g_exit[dir][0], 1u);
        if (j == 0) {
            while (ld_acq(&g_exit[dir][0]) < (unsigned)RCTAS) { }
            g_cnt[dir][0] = 0u;
            __threadfence();
            atomicExch(&g_exit[dir][0], 0u);
        }
    }
}

// ---------------- pairwise MLP edge scores ----------------
__global__ void pair_score(const float* __restrict__ b1, const float* __restrict__ W2,
                           const float* __restrict__ b2) {
    __shared__ float Sh[32][101];
    __shared__ float Sm[32][101];
    __shared__ float sb1[MLPH], sw2[MLPH];
    int bh = blockIdx.y * 32, bm = blockIdx.x * 32;
    int tid = threadIdx.x;
    for (int i = tid; i < 32 * MLPH; i += 256) {
        int r = i / MLPH, c = i % MLPH;
        Sh[r][c] = g_sh[(size_t)(bh + r) * MLPH + c];
        Sm[r][c] = g_sm[(size_t)(bm + r) * MLPH + c];
    }
    if (tid < MLPH) { sb1[tid] = b1[tid]; sw2[tid] = W2[tid]; }
    __syncthreads();

    int tx = tid & 15, ty = tid >> 4;
    int h0 = ty * 2, m0 = tx * 2;
    float acc00 = 0.f, acc01 = 0.f, acc10 = 0.f, acc11 = 0.f;
    for (int jx = 0; jx < MLPH; jx++) {
        float w = sw2[jx], bb = sb1[jx];
        float a0 = Sh[h0][jx] + bb;
        float a1 = Sh[h0 + 1][jx] + bb;
        float c0 = Sm[m0][jx];
        float c1 = Sm[m0 + 1][jx];
        acc00 = fmaf(tanhap(a0 + c0), w, acc00);
        acc01 = fmaf(tanhap(a0 + c1), w, acc01);
        acc10 = fmaf(tanhap(a1 + c0), w, acc10);
        acc11 = fmaf(tanhap(a1 + c1), w, acc11);
    }
    float b2v = __ldg(b2);
    g_scores[(size_t)(bh + h0) * SEQ + bm + m0]         = acc00 + b2v;
    g_scores[(size_t)(bh + h0) * SEQ + bm + m0 + 1]     = acc01 + b2v;
    g_scores[(size_t)(bh + h0 + 1) * SEQ + bm + m0]     = acc10 + b2v;
    g_scores[(size_t)(bh + h0 + 1) * SEQ + bm + m0 + 1] = acc11 + b2v;
}

// ---------------- softmax over axis 0 ----------------
__global__ void softmax0(float* __restrict__ out) {
    int m = blockIdx.x;
    int tid = threadIdx.x;  // 128
    float v[4];
#pragma unroll
    for (int i = 0; i < 4; i++) v[i] = g_scores[(size_t)(tid + 128 * i) * SEQ + m];
    float mx = fmaxf(fmaxf(v[0], v[1]), fmaxf(v[2], v[3]));
    __shared__ float red[128];
    red[tid] = mx; __syncthreads();
    for (int o = 64; o > 0; o >>= 1) {
        if (tid < o) red[tid] = fmaxf(red[tid], red[tid + o]);
        __syncthreads();
    }
    mx = red[0]; __syncthreads();
    float e[4]; float ssum = 0.f;
#pragma unroll
    for (int i = 0; i < 4; i++) { e[i] = __expf(v[i] - mx); ssum += e[i]; }
    red[tid] = ssum; __syncthreads();
    for (int o = 64; o > 0; o >>= 1) {
        if (tid < o) red[tid] += red[tid + o];
        __syncthreads();
    }
    float inv = 1.f / red[0];
#pragma unroll
    for (int i = 0; i < 4; i++) out[(size_t)(tid + 128 * i) * SEQ + m] = e[i] * inv;
}

// ---------------- launch ----------------
extern "C" void kernel_launch(void* const* d_in, const int* in_sizes, int n_in,
                              void* d_out, int out_size) {
    const int*   wi  = (const int*)d_in[0];
    const int*   pi  = (const int*)d_in[1];
    const float* we  = (const float*)d_in[2];
    const float* pe  = (const float*)d_in[3];
    const float* wih0f = (const float*)d_in[4];
    const float* whh0f = (const float*)d_in[5];
    const float* b0f   = (const float*)d_in[6];
    const float* wih0b = (const float*)d_in[7];
    const float* whh0b = (const float*)d_in[8];
    const float* b0b   = (const float*)d_in[9];
    const float* wih1f = (const float*)d_in[10];
    const float* whh1f = (const float*)d_in[11];
    const float* b1f   = (const float*)d_in[12];
    const float* wih1b = (const float*)d_in[13];
    const float* whh1b = (const float*)d_in[14];
    const float* b1b   = (const float*)d_in[15];
    const float* W1    = (const float*)d_in[16];
    const float* b1    = (const float*)d_in[17];
    const float* W2    = (const float*)d_in[18];
    const float* b2    = (const float*)d_in[19];
    float* out = (float*)d_out;

    float *p_x0, *p_xw0, *p_xw1, *p_h0, *p_h1, *p_sh, *p_sm;
    cudaGetSymbolAddress((void**)&p_x0, g_x0);
    cudaGetSymbolAddress((void**)&p_xw0, g_xw0);
    cudaGetSymbolAddress((void**)&p_xw1, g_xw1);
    cudaGetSymbolAddress((void**)&p_h0, g_h0);
    cudaGetSymbolAddress((void**)&p_h1, g_h1);
    cudaGetSymbolAddress((void**)&p_sh, g_sh);
    cudaGetSymbolAddress((void**)&p_sm, g_sm);

    // 1. embeddings
    embed_kernel<<<SEQ, 256>>>(wi, pi, we, pe);

    // 2. layer0 input GEMMs (both directions in one launch)
    {
        dim3 grid(GATES / 128, SEQ / 128, 2);
        gemm_dual<<<grid, 256>>>(p_x0, IN0, wih0f, wih0b, IN0, b0f, b0b,
                                 p_xw0, p_xw1, GATES, SEQ, GATES, IN0);
    }

    // 3. layer0 recurrence
    lstm_layer<<<2 * RCTAS, 256>>>(whh0f, whh0b, p_xw0, p_xw1, p_h0);

    // 4. layer1 input GEMMs (both directions in one launch)
    {
        dim3 grid(GATES / 128, SEQ / 128, 2);
        gemm_dual<<<grid, 256>>>(p_h0, IN1, wih1f, wih1b, IN1, b1f, b1b,
                                 p_xw0, p_xw1, GATES, SEQ, GATES, IN1);
    }

    // 5. layer1 recurrence
    lstm_layer<<<2 * RCTAS, 256>>>(whh1f, whh1b, p_xw0, p_xw1, p_h1);

    // 6. MLP projections, both halves in one launch (W1 is [100, 2048] -> ldb = PAIRD)
    {
        dim3 grid((MLPH + 127) / 128, SEQ / 128, 2);
        gemm_dual<<<grid, 256>>>(p_h1, 2 * HID, W1, W1 + 1024, PAIRD, nullptr, nullptr,
                                 p_sh, p_sm, MLPH, SEQ, MLPH, 2 * HID);
    }

    // 7. pairwise scores
    {
        dim3 grid(SEQ / 32, SEQ / 32);
        pair_score<<<grid, 256>>>(b1, W2, b2);
    }

    // 8. softmax over heads (axis 0)
    softmax0<<<SEQ, 128>>>(out);
}

// round 11
// speedup vs baseline: 1.1255x; 1.1255x over previous
#include <cuda_runtime.h>
#include <math.h>
#include <stdint.h>

#define SEQ   512
#define HID   512
#define IN0   1088
#define IN1   1024
#define GATES 2048
#define MLPH  100
#define PAIRD 2048
#define RCTAS 64   // CTAs per LSTM direction
#define WIN   1.5f

// ---------------- device scratch (no allocations allowed) ----------------
__device__ float g_x0[SEQ * IN0];
__device__ float g_xw0[SEQ * GATES];
__device__ float g_xw1[SEQ * GATES];
__device__ float g_h0[SEQ * 2 * HID];
__device__ float g_h1[SEQ * 2 * HID];
__device__ float g_sh[SEQ * MLPH];
__device__ float g_sm[SEQ * MLPH];
__device__ float g_scores[SEQ * SEQ];
// self-validating h exchange: [dir][buffer=t&1][granule 0..255] (8B = 2 h values)
__device__ __align__(128) unsigned long long g_hx[2][2][256];
__device__ __align__(128) unsigned g_cnt[2][32];    // one-time start barrier
__device__ __align__(128) unsigned g_exit[2][32];   // exit/reset barrier

// ---------------- helpers ----------------
__device__ __forceinline__ unsigned ld_acq(const unsigned* p) {
    unsigned v;
    asm volatile("ld.acquire.gpu.u32 %0, [%1];" : "=r"(v) : "l"(p) : "memory");
    return v;
}
__device__ __forceinline__ unsigned long long ld_rlx64(const unsigned long long* p) {
    unsigned long long v;
    asm volatile("ld.relaxed.gpu.global.b64 %0, [%1];" : "=l"(v) : "l"(p) : "memory");
    return v;
}
__device__ __forceinline__ void st_rlx64(unsigned long long* p, unsigned long long v) {
    asm volatile("st.relaxed.gpu.global.b64 [%0], %1;" :: "l"(p), "l"(v) : "memory");
}
__device__ __forceinline__ float tanhap(float x) {             // HW tanh
    float y;
    asm("tanh.approx.f32 %0, %1;" : "=f"(y) : "f"(x));
    return y;
}
__device__ __forceinline__ float sigap(float x) {              // sigmoid via HW tanh
    return fmaf(0.5f, tanhap(0.5f * x), 0.5f);
}

// ---------------- embeddings ----------------
__global__ void embed_kernel(const int* __restrict__ wi, const int* __restrict__ pi,
                             const float* __restrict__ we, const float* __restrict__ pe) {
    int t = blockIdx.x;
    int w = wi[t], p = pi[t];
    const float* wr = we + (size_t)w * 1024;
    const float* pr = pe + (size_t)p * 64;
    float* out = g_x0 + (size_t)t * IN0;
    for (int i = threadIdx.x; i < 1024; i += blockDim.x) out[i] = wr[i];
    for (int i = threadIdx.x; i < 64; i += blockDim.x) out[1024 + i] = pr[i];
}

// ---- dual GEMM: z selects (B, bias, C); C[M,N] = A[M,K] * B[N,K]^T (+bias) ----
// BM=64, BN=64, BK=16, 256 threads, 4x4 register tile, register double-buffered.
// (R9-winning config — 128x128 variant starved the N=100 MLP gemm of CTAs.)
__global__ void gemm_dual(const float* __restrict__ A, int lda,
                          const float* __restrict__ B0, const float* __restrict__ B1, int ldb,
                          const float* __restrict__ bias0, const float* __restrict__ bias1,
                          float* __restrict__ C0, float* __restrict__ C1, int ldc,
                          int M, int N, int K) {
    const float* B = blockIdx.z ? B1 : B0;
    const float* bias = blockIdx.z ? bias1 : bias0;
    float* C = blockIdx.z ? C1 : C0;

    __shared__ __align__(16) float As[16][68];
    __shared__ __align__(16) float Bs[16][68];
    int bm = blockIdx.y * 64, bn = blockIdx.x * 64;
    int tid = threadIdx.x;
    int tx = tid & 15, ty = tid >> 4;
    int lr = tid >> 2;
    int lk = (tid & 3) * 4;

    float acc[4][4];
#pragma unroll
    for (int i = 0; i < 4; i++)
#pragma unroll
        for (int j = 0; j < 4; j++) acc[i][j] = 0.f;

    int rowa = bm + lr;
    int rowb = bn + lr;

    // preload tile 0
    float4 va = make_float4(0.f, 0.f, 0.f, 0.f);
    float4 vb = make_float4(0.f, 0.f, 0.f, 0.f);
    if (rowa < M) va = *(const float4*)(A + (size_t)rowa * lda + lk);
    if (rowb < N) vb = *(const float4*)(B + (size_t)rowb * ldb + lk);

    for (int k0 = 0; k0 < K; k0 += 16) {
        As[lk + 0][lr] = va.x; As[lk + 1][lr] = va.y; As[lk + 2][lr] = va.z; As[lk + 3][lr] = va.w;
        Bs[lk + 0][lr] = vb.x; Bs[lk + 1][lr] = vb.y; Bs[lk + 2][lr] = vb.z; Bs[lk + 3][lr] = vb.w;
        __syncthreads();
        // prefetch next tile while computing
        if (k0 + 16 < K) {
            va = make_float4(0.f, 0.f, 0.f, 0.f);
            vb = make_float4(0.f, 0.f, 0.f, 0.f);
            if (rowa < M) va = *(const float4*)(A + (size_t)rowa * lda + k0 + 16 + lk);
            if (rowb < N) vb = *(const float4*)(B + (size_t)rowb * ldb + k0 + 16 + lk);
        }
#pragma unroll
        for (int k = 0; k < 16; k++) {
            float4 a4 = *(const float4*)&As[k][ty * 4];
            float4 b4 = *(const float4*)&Bs[k][tx * 4];
            float a[4] = {a4.x, a4.y, a4.z, a4.w};
            float b[4] = {b4.x, b4.y, b4.z, b4.w};
#pragma unroll
            for (int i = 0; i < 4; i++)
#pragma unroll
                for (int j = 0; j < 4; j++) acc[i][j] = fmaf(a[i], b[j], acc[i][j]);
        }
        __syncthreads();
    }
#pragma unroll
    for (int i = 0; i < 4; i++) {
        int r = bm + ty * 4 + i;
        if (r >= M) continue;
#pragma unroll
        for (int j = 0; j < 4; j++) {
            int c = bn + tx * 4 + j;
            if (c < N) C[(size_t)r * ldc + c] = acc[i][j] + (bias ? bias[c] : 0.f);
        }
    }
}

// ---------------- LSTM recurrence: warp-private h slices + self-validating exchange -----
// grid = 128 CTAs (64 fwd, 64 bwd), 256 threads. CTA owns 8 h-indices (32 gate rows).
// Warp ck consumes ONLY h[64ck..64ck+63] (granules 32ck..32ck+31, produced by CTAs
// 8ck..8ck+7): its sh slice is warp-private, so the pre-matvec block barrier is
// replaced by a per-warp poll + __syncwarp. Gate/publish phase unchanged from R7.
__global__ void __launch_bounds__(256, 1)
lstm_layer(const float* __restrict__ whh_f, const float* __restrict__ whh_b,
           const float* __restrict__ xw_f, const float* __restrict__ xw_b,
           float* __restrict__ hout) {
    __shared__ float sh[512];
    __shared__ float zp[32 * 9];
    __shared__ float sact[32];

    int dir = blockIdx.x >> 6;
    int j = blockIdx.x & 63;
    int hbase = j * 8;
    const float* W = dir ? whh_b : whh_f;
    const float* xw = dir ? xw_b : xw_f;
    int tid = threadIdx.x;
    int lane = tid & 31;

    int row = tid & 31;            // gate row within CTA (0..31)
    int ck = tid >> 5;             // K chunk == warp id (0..7)
    const int base = ck * 64;

    // weights into registers
    float w[64];
    {
        const float* src = W + (size_t)((row >> 3) * 512 + hbase + (row & 7)) * 512 + base;
#pragma unroll
        for (int i = 0; i < 64; i += 4) {
            float4 v = *(const float4*)(src + i);
            w[i] = v.x; w[i + 1] = v.y; w[i + 2] = v.z; w[i + 3] = v.w;
        }
    }

    // one-time: poison own hx granules, then grid start-barrier (per direction)
    if (tid == 0) {
        unsigned long long poison =
            ((unsigned long long)__float_as_uint(1e30f) << 32) | __float_as_uint(1e30f);
#pragma unroll
        for (int b = 0; b < 2; b++)
#pragma unroll
            for (int q = 0; q < 4; q++)
                st_rlx64(&g_hx[dir][b][j * 4 + q], poison);
        __threadfence();
        atomicAdd(&g_cnt[dir][0], 1u);
        while (ld_acq(&g_cnt[dir][0]) < (unsigned)RCTAS) { }
    }
    __syncthreads();

    float c_state = 0.f;           // owned by threads 0..7
    int kp = 0, kc = 0;            // t mod 7 (producer), (t-1) mod 7 (consumer)
    const int gran = ck * 32 + lane;   // this lane's granule (warp-private slice)

    for (int t = 0; t < 512; t++) {
        int pos = dir ? (511 - t) : t;
        float coffp = 4.0f * (float)kp;
        float coffc = 4.0f * (float)kc;

        // prefetch gate inputs (independent of h) — overlaps the poll below
        float xg = 0.f;
        if (tid < 32) {
            const float* xr = xw + (size_t)pos * GATES + (tid >> 3) * 512 + hbase + (tid & 7);
            xg = __ldg(xr);
        }

        // per-warp gather: lane polls its warp's granule; sh slice is warp-private
        if (t == 0) {
            ((float2*)sh)[gran] = make_float2(0.f, 0.f);
        } else {
            const unsigned long long* src = &g_hx[dir][(t - 1) & 1][gran];
            float lo, hi;
            for (;;) {
                unsigned long long v = ld_rlx64(src);
                lo = __uint_as_float((unsigned)v);
                hi = __uint_as_float((unsigned)(v >> 32));
                if (fabsf(lo - coffc) <= WIN && fabsf(hi - coffc) <= WIN) break;
            }
            ((float2*)sh)[gran] = make_float2(lo - coffc, hi - coffc);
        }
        __syncwarp();      // warp-local: this warp's sh slice ready

        // matvec partial: register weights x warp-private smem h slice
        {
            const float* hv = sh + base;
            float a0 = 0.f, a1 = 0.f, a2 = 0.f, a3 = 0.f;
#pragma unroll
            for (int i = 0; i < 64; i += 4) {
                float4 h4 = *(const float4*)(hv + i);
                a0 = fmaf(w[i + 0], h4.x, a0);
                a1 = fmaf(w[i + 1], h4.y, a1);
                a2 = fmaf(w[i + 2], h4.z, a2);
                a3 = fmaf(w[i + 3], h4.w, a3);
            }
            zp[row * 9 + ck] = (a0 + a1) + (a2 + a3);
        }
        __syncthreads();   // zp ready (block-wide)

        // warp 0: gate-row sums + activations; 8 owners update state + publish
        if (tid < 32) {
            const float* zr = zp + tid * 9;
            float z = xg;
#pragma unroll
            for (int c = 0; c < 8; c++) z += zr[c];
            sact[tid] = ((tid >> 3) == 2) ? tanhap(z) : sigap(z);
        }
        __syncwarp();
        if (tid < 8) {
            float gi = sact[tid];
            float gf = sact[8 + tid];
            float gg = sact[16 + tid];
            float go_ = sact[24 + tid];
            c_state = gf * c_state + gi * gg;
            float h = go_ * tanhap(c_state);
            __stcg(hout + (size_t)pos * 1024 + (dir << 9) + hbase + tid, h);
            // publish: v = h + 4*(t%7), packed 2-per-b64, fire-and-forget
            float vv = h + coffp;
            float partner = __shfl_xor_sync(0x000000FFu, vv, 1);
            if ((tid & 1) == 0) {
                unsigned long long pk =
                    ((unsigned long long)__float_as_uint(partner) << 32) | __float_as_uint(vv);
                st_rlx64(&g_hx[dir][t & 1][j * 4 + (tid >> 1)], pk);
            }
        }
        kc = kp;
        kp = (kp == 6) ? 0 : kp + 1;
    }

    // exit/reset: make counters zero for the next launch / graph replay
    __syncthreads();
    if (tid == 0) {
        __threadfence();
        atomicAdd(&g_exit[dir][0], 1u);
        if (j == 0) {
            while (ld_acq(&g_exit[dir][0]) < (unsigned)RCTAS) { }
            g_cnt[dir][0] = 0u;
            __threadfence();
            atomicExch(&g_exit[dir][0], 0u);
        }
    }
}

// ---------------- pairwise MLP edge scores ----------------
__global__ void pair_score(const float* __restrict__ b1, const float* __restrict__ W2,
                           const float* __restrict__ b2) {
    __shared__ float Sh[32][101];
    __shared__ float Sm[32][101];
    __shared__ float sb1[MLPH], sw2[MLPH];
    int bh = blockIdx.y * 32, bm = blockIdx.x * 32;
    int tid = threadIdx.x;
    for (int i = tid; i < 32 * MLPH; i += 256) {
        int r = i / MLPH, c = i % MLPH;
        Sh[r][c] = g_sh[(size_t)(bh + r) * MLPH + c];
        Sm[r][c] = g_sm[(size_t)(bm + r) * MLPH + c];
    }
    if (tid < MLPH) { sb1[tid] = b1[tid]; sw2[tid] = W2[tid]; }
    __syncthreads();

    int tx = tid & 15, ty = tid >> 4;
    int h0 = ty * 2, m0 = tx * 2;
    float acc00 = 0.f, acc01 = 0.f, acc10 = 0.f, acc11 = 0.f;
    for (int jx = 0; jx < MLPH; jx++) {
        float w = sw2[jx], bb = sb1[jx];
        float a0 = Sh[h0][jx] + bb;
        float a1 = Sh[h0 + 1][jx] + bb;
        float c0 = Sm[m0][jx];
        float c1 = Sm[m0 + 1][jx];
        acc00 = fmaf(tanhap(a0 + c0), w, acc00);
        acc01 = fmaf(tanhap(a0 + c1), w, acc01);
        acc10 = fmaf(tanhap(a1 + c0), w, acc10);
        acc11 = fmaf(tanhap(a1 + c1), w, acc11);
    }
    float b2v = __ldg(b2);
    g_scores[(size_t)(bh + h0) * SEQ + bm + m0]         = acc00 + b2v;
    g_scores[(size_t)(bh + h0) * SEQ + bm + m0 + 1]     = acc01 + b2v;
    g_scores[(size_t)(bh + h0 + 1) * SEQ + bm + m0]     = acc10 + b2v;
    g_scores[(size_t)(bh + h0 + 1) * SEQ + bm + m0 + 1] = acc11 + b2v;
}

// ---------------- softmax over axis 0 ----------------
__global__ void softmax0(float* __restrict__ out) {
    int m = blockIdx.x;
    int tid = threadIdx.x;  // 128
    float v[4];
#pragma unroll
    for (int i = 0; i < 4; i++) v[i] = g_scores[(size_t)(tid + 128 * i) * SEQ + m];
    float mx = fmaxf(fmaxf(v[0], v[1]), fmaxf(v[2], v[3]));
    __shared__ float red[128];
    red[tid] = mx; __syncthreads();
    for (int o = 64; o > 0; o >>= 1) {
        if (tid < o) red[tid] = fmaxf(red[tid], red[tid + o]);
        __syncthreads();
    }
    mx = red[0]; __syncthreads();
    float e[4]; float ssum = 0.f;
#pragma unroll
    for (int i = 0; i < 4; i++) { e[i] = __expf(v[i] - mx); ssum += e[i]; }
    red[tid] = ssum; __syncthreads();
    for (int o = 64; o > 0; o >>= 1) {
        if (tid < o) red[tid] += red[tid + o];
        __syncthreads();
    }
    float inv = 1.f / red[0];
#pragma unroll
    for (int i = 0; i < 4; i++) out[(size_t)(tid + 128 * i) * SEQ + m] = e[i] * inv;
}

// ---------------- launch ----------------
extern "C" void kernel_launch(void* const* d_in, const int* in_sizes, int n_in,
                              void* d_out, int out_size) {
    const int*   wi  = (const int*)d_in[0];
    const int*   pi  = (const int*)d_in[1];
    const float* we  = (const float*)d_in[2];
    const float* pe  = (const float*)d_in[3];
    const float* wih0f = (const float*)d_in[4];
    const float* whh0f = (const float*)d_in[5];
    const float* b0f   = (const float*)d_in[6];
    const float* wih0b = (const float*)d_in[7];
    const float* whh0b = (const float*)d_in[8];
    const float* b0b   = (const float*)d_in[9];
    const float* wih1f = (const float*)d_in[10];
    const float* whh1f = (const float*)d_in[11];
    const float* b1f   = (const float*)d_in[12];
    const float* wih1b = (const float*)d_in[13];
    const float* whh1b = (const float*)d_in[14];
    const float* b1b   = (const float*)d_in[15];
    const float* W1    = (const float*)d_in[16];
    const float* b1    = (const float*)d_in[17];
    const float* W2    = (const float*)d_in[18];
    const float* b2    = (const float*)d_in[19];
    float* out = (float*)d_out;

    float *p_x0, *p_xw0, *p_xw1, *p_h0, *p_h1, *p_sh, *p_sm;
    cudaGetSymbolAddress((void**)&p_x0, g_x0);
    cudaGetSymbolAddress((void**)&p_xw0, g_xw0);
    cudaGetSymbolAddress((void**)&p_xw1, g_xw1);
    cudaGetSymbolAddress((void**)&p_h0, g_h0);
    cudaGetSymbolAddress((void**)&p_h1, g_h1);
    cudaGetSymbolAddress((void**)&p_sh, g_sh);
    cudaGetSymbolAddress((void**)&p_sm, g_sm);

    // 1. embeddings
    embed_kernel<<<SEQ, 256>>>(wi, pi, we, pe);

    // 2. layer0 input GEMMs (both directions in one launch)
    {
        dim3 grid(GATES / 64, SEQ / 64, 2);
        gemm_dual<<<grid, 256>>>(p_x0, IN0, wih0f, wih0b, IN0, b0f, b0b,
                                 p_xw0, p_xw1, GATES, SEQ, GATES, IN0);
    }

    // 3. layer0 recurrence
    lstm_layer<<<2 * RCTAS, 256>>>(whh0f, whh0b, p_xw0, p_xw1, p_h0);

    // 4. layer1 input GEMMs (both directions in one launch)
    {
        dim3 grid(GATES / 64, SEQ / 64, 2);
        gemm_dual<<<grid, 256>>>(p_h0, IN1, wih1f, wih1b, IN1, b1f, b1b,
                                 p_xw0, p_xw1, GATES, SEQ, GATES, IN1);
    }

    // 5. layer1 recurrence
    lstm_layer<<<2 * RCTAS, 256>>>(whh1f, whh1b, p_xw0, p_xw1, p_h1);

    // 6. MLP projections, both halves in one launch (W1 is [100, 2048] -> ldb = PAIRD)
    {
        dim3 grid((MLPH + 63) / 64, SEQ / 64, 2);
        gemm_dual<<<grid, 256>>>(p_h1, 2 * HID, W1, W1 + 1024, PAIRD, nullptr, nullptr,
                                 p_sh, p_sm, MLPH, SEQ, MLPH, 2 * HID);
    }

    // 7. pairwise scores
    {
        dim3 grid(SEQ / 32, SEQ / 32);
        pair_score<<<grid, 256>>>(b1, W2, b2);
    }

    // 8. softmax over heads (axis 0)
    softmax0<<<SEQ, 128>>>(out);
}

// round 12
// speedup vs baseline: 1.1794x; 1.0480x over previous
#include <cuda_runtime.h>
#include <math.h>
#include <stdint.h>

#define SEQ   512
#define HID   512
#define IN0   1088
#define IN1   1024
#define GATES 2048
#define MLPH  100
#define PAIRD 2048
#define RCTAS 64   // CTAs per LSTM direction
#define WIN   1.5f

// ---------------- device scratch (no allocations allowed) ----------------
__device__ float g_x0[SEQ * IN0];
__device__ float g_xw0[SEQ * GATES];
__device__ float g_xw1[SEQ * GATES];
__device__ float g_h0[SEQ * 2 * HID];
__device__ float g_h1[SEQ * 2 * HID];
__device__ float g_sh[SEQ * MLPH];
__device__ float g_sm[SEQ * MLPH];
__device__ float g_scores[SEQ * SEQ];
// self-validating h exchange: [dir][buffer=t&1][granule 0..255] (8B = 2 h values)
__device__ __align__(128) unsigned long long g_hx[2][2][256];
__device__ __align__(128) unsigned g_cnt[2][32];    // one-time start barrier
__device__ __align__(128) unsigned g_exit[2][32];   // exit/reset barrier

// ---------------- helpers ----------------
__device__ __forceinline__ unsigned ld_acq(const unsigned* p) {
    unsigned v;
    asm volatile("ld.acquire.gpu.u32 %0, [%1];" : "=r"(v) : "l"(p) : "memory");
    return v;
}
__device__ __forceinline__ unsigned long long ld_rlx64(const unsigned long long* p) {
    unsigned long long v;
    asm volatile("ld.relaxed.gpu.global.b64 %0, [%1];" : "=l"(v) : "l"(p) : "memory");
    return v;
}
__device__ __forceinline__ void st_rlx64(unsigned long long* p, unsigned long long v) {
    asm volatile("st.relaxed.gpu.global.b64 [%0], %1;" :: "l"(p), "l"(v) : "memory");
}
__device__ __forceinline__ float tanhap(float x) {             // HW tanh
    float y;
    asm("tanh.approx.f32 %0, %1;" : "=f"(y) : "f"(x));
    return y;
}
__device__ __forceinline__ float sigap(float x) {              // sigmoid via HW tanh
    return fmaf(0.5f, tanhap(0.5f * x), 0.5f);
}

// ---------------- embeddings ----------------
__global__ void embed_kernel(const int* __restrict__ wi, const int* __restrict__ pi,
                             const float* __restrict__ we, const float* __restrict__ pe) {
    int t = blockIdx.x;
    int w = wi[t], p = pi[t];
    const float* wr = we + (size_t)w * 1024;
    const float* pr = pe + (size_t)p * 64;
    float* out = g_x0 + (size_t)t * IN0;
    for (int i = threadIdx.x; i < 1024; i += blockDim.x) out[i] = wr[i];
    for (int i = threadIdx.x; i < 64; i += blockDim.x) out[1024 + i] = pr[i];
}

// ---- big dual GEMM: BM=128, BN=64, BK=16, 256 threads, 8x4 register tile ----
// 3 LDS.128 per 32 FMAs (1.5x better FMA/LDS ratio than the 4x4 kernel which was
// L1-bound at 76%). Used for the SEQ x GATES x K input GEMMs only.
__global__ void __launch_bounds__(256, 1)
gemm_big(const float* __restrict__ A, int lda,
         const float* __restrict__ B0, const float* __restrict__ B1, int ldb,
         const float* __restrict__ bias0, const float* __restrict__ bias1,
         float* __restrict__ C0, float* __restrict__ C1, int ldc,
         int M, int N, int K) {
    const float* B = blockIdx.z ? B1 : B0;
    const float* bias = blockIdx.z ? bias1 : bias0;
    float* C = blockIdx.z ? C1 : C0;

    __shared__ __align__(16) float As[16][132];
    __shared__ __align__(16) float Bs[16][68];
    int bm = blockIdx.y * 128, bn = blockIdx.x * 64;
    int tid = threadIdx.x;
    int tx = tid & 15, ty = tid >> 4;          // 16 x 16 thread grid: ty->8 rows, tx->4 cols
    int lrA = tid >> 1;                        // 0..127
    int lkA = (tid & 1) * 8;                   // 0 or 8
    int lrB = tid >> 2;                        // 0..63
    int lkB = (tid & 3) * 4;                   // 0,4,8,12

    float acc[8][4];
#pragma unroll
    for (int i = 0; i < 8; i++)
#pragma unroll
        for (int j = 0; j < 4; j++) acc[i][j] = 0.f;

    int rowa = bm + lrA;
    int rowb = bn + lrB;
    bool a_ok = rowa < M;
    bool b_ok = rowb < N;

    // preload tile 0
    float4 va0 = make_float4(0.f, 0.f, 0.f, 0.f), va1 = va0, vb = va0;
    if (a_ok) {
        const float* p = A + (size_t)rowa * lda + lkA;
        va0 = *(const float4*)p; va1 = *(const float4*)(p + 4);
    }
    if (b_ok) vb = *(const float4*)(B + (size_t)rowb * ldb + lkB);

    for (int k0 = 0; k0 < K; k0 += 16) {
        As[lkA + 0][lrA] = va0.x; As[lkA + 1][lrA] = va0.y; As[lkA + 2][lrA] = va0.z; As[lkA + 3][lrA] = va0.w;
        As[lkA + 4][lrA] = va1.x; As[lkA + 5][lrA] = va1.y; As[lkA + 6][lrA] = va1.z; As[lkA + 7][lrA] = va1.w;
        Bs[lkB + 0][lrB] = vb.x; Bs[lkB + 1][lrB] = vb.y; Bs[lkB + 2][lrB] = vb.z; Bs[lkB + 3][lrB] = vb.w;
        __syncthreads();
        // prefetch next tile while computing
        if (k0 + 16 < K) {
            if (a_ok) {
                const float* p = A + (size_t)rowa * lda + k0 + 16 + lkA;
                va0 = *(const float4*)p; va1 = *(const float4*)(p + 4);
            }
            if (b_ok) vb = *(const float4*)(B + (size_t)rowb * ldb + k0 + 16 + lkB);
        }
#pragma unroll
        for (int k = 0; k < 16; k++) {
            float a[8], b[4];
            *(float4*)&a[0] = *(const float4*)&As[k][ty * 8];
            *(float4*)&a[4] = *(const float4*)&As[k][ty * 8 + 4];
            *(float4*)&b[0] = *(const float4*)&Bs[k][tx * 4];
#pragma unroll
            for (int i = 0; i < 8; i++)
#pragma unroll
                for (int j = 0; j < 4; j++) acc[i][j] = fmaf(a[i], b[j], acc[i][j]);
        }
        __syncthreads();
    }
#pragma unroll
    for (int i = 0; i < 8; i++) {
        int r = bm + ty * 8 + i;
        if (r >= M) continue;
#pragma unroll
        for (int j = 0; j < 4; j++) {
            int c = bn + tx * 4 + j;
            if (c < N) C[(size_t)r * ldc + c] = acc[i][j] + (bias ? bias[c] : 0.f);
        }
    }
}

// ---- dual GEMM: BM=64, BN=64, BK=16, 256 threads, 4x4 tile (kept for N=100 MLP) ----
__global__ void gemm_dual(const float* __restrict__ A, int lda,
                          const float* __restrict__ B0, const float* __restrict__ B1, int ldb,
                          const float* __restrict__ bias0, const float* __restrict__ bias1,
                          float* __restrict__ C0, float* __restrict__ C1, int ldc,
                          int M, int N, int K) {
    const float* B = blockIdx.z ? B1 : B0;
    const float* bias = blockIdx.z ? bias1 : bias0;
    float* C = blockIdx.z ? C1 : C0;

    __shared__ __align__(16) float As[16][68];
    __shared__ __align__(16) float Bs[16][68];
    int bm = blockIdx.y * 64, bn = blockIdx.x * 64;
    int tid = threadIdx.x;
    int tx = tid & 15, ty = tid >> 4;
    int lr = tid >> 2;
    int lk = (tid & 3) * 4;

    float acc[4][4];
#pragma unroll
    for (int i = 0; i < 4; i++)
#pragma unroll
        for (int j = 0; j < 4; j++) acc[i][j] = 0.f;

    int rowa = bm + lr;
    int rowb = bn + lr;

    float4 va = make_float4(0.f, 0.f, 0.f, 0.f);
    float4 vb = make_float4(0.f, 0.f, 0.f, 0.f);
    if (rowa < M) va = *(const float4*)(A + (size_t)rowa * lda + lk);
    if (rowb < N) vb = *(const float4*)(B + (size_t)rowb * ldb + lk);

    for (int k0 = 0; k0 < K; k0 += 16) {
        As[lk + 0][lr] = va.x; As[lk + 1][lr] = va.y; As[lk + 2][lr] = va.z; As[lk + 3][lr] = va.w;
        Bs[lk + 0][lr] = vb.x; Bs[lk + 1][lr] = vb.y; Bs[lk + 2][lr] = vb.z; Bs[lk + 3][lr] = vb.w;
        __syncthreads();
        if (k0 + 16 < K) {
            va = make_float4(0.f, 0.f, 0.f, 0.f);
            vb = make_float4(0.f, 0.f, 0.f, 0.f);
            if (rowa < M) va = *(const float4*)(A + (size_t)rowa * lda + k0 + 16 + lk);
            if (rowb < N) vb = *(const float4*)(B + (size_t)rowb * ldb + k0 + 16 + lk);
        }
#pragma unroll
        for (int k = 0; k < 16; k++) {
            float4 a4 = *(const float4*)&As[k][ty * 4];
            float4 b4 = *(const float4*)&Bs[k][tx * 4];
            float a[4] = {a4.x, a4.y, a4.z, a4.w};
            float b[4] = {b4.x, b4.y, b4.z, b4.w};
#pragma unroll
            for (int i = 0; i < 4; i++)
#pragma unroll
                for (int j = 0; j < 4; j++) acc[i][j] = fmaf(a[i], b[j], acc[i][j]);
        }
        __syncthreads();
    }
#pragma unroll
    for (int i = 0; i < 4; i++) {
        int r = bm + ty * 4 + i;
        if (r >= M) continue;
#pragma unroll
        for (int j = 0; j < 4; j++) {
            int c = bn + tx * 4 + j;
            if (c < N) C[(size_t)r * ldc + c] = acc[i][j] + (bias ? bias[c] : 0.f);
        }
    }
}

// ---------------- LSTM recurrence: warp-private h slices + self-validating exchange -----
// (R11-winning structure — protected)
__global__ void __launch_bounds__(256, 1)
lstm_layer(const float* __restrict__ whh_f, const float* __restrict__ whh_b,
           const float* __restrict__ xw_f, const float* __restrict__ xw_b,
           float* __restrict__ hout) {
    __shared__ float sh[512];
    __shared__ float zp[32 * 9];
    __shared__ float sact[32];

    int dir = blockIdx.x >> 6;
    int j = blockIdx.x & 63;
    int hbase = j * 8;
    const float* W = dir ? whh_b : whh_f;
    const float* xw = dir ? xw_b : xw_f;
    int tid = threadIdx.x;
    int lane = tid & 31;

    int row = tid & 31;            // gate row within CTA (0..31)
    int ck = tid >> 5;             // K chunk == warp id (0..7)
    const int base = ck * 64;

    // weights into registers
    float w[64];
    {
        const float* src = W + (size_t)((row >> 3) * 512 + hbase + (row & 7)) * 512 + base;
#pragma unroll
        for (int i = 0; i < 64; i += 4) {
            float4 v = *(const float4*)(src + i);
            w[i] = v.x; w[i + 1] = v.y; w[i + 2] = v.z; w[i + 3] = v.w;
        }
    }

    // one-time: poison own hx granules, then grid start-barrier (per direction)
    if (tid == 0) {
        unsigned long long poison =
            ((unsigned long long)__float_as_uint(1e30f) << 32) | __float_as_uint(1e30f);
#pragma unroll
        for (int b = 0; b < 2; b++)
#pragma unroll
            for (int q = 0; q < 4; q++)
                st_rlx64(&g_hx[dir][b][j * 4 + q], poison);
        __threadfence();
        atomicAdd(&g_cnt[dir][0], 1u);
        while (ld_acq(&g_cnt[dir][0]) < (unsigned)RCTAS) { }
    }
    __syncthreads();

    float c_state = 0.f;           // owned by threads 0..7
    int kp = 0, kc = 0;            // t mod 7 (producer), (t-1) mod 7 (consumer)
    const int gran = ck * 32 + lane;   // this lane's granule (warp-private slice)

    for (int t = 0; t < 512; t++) {
        int pos = dir ? (511 - t) : t;
        float coffp = 4.0f * (float)kp;
        float coffc = 4.0f * (float)kc;

        // prefetch gate inputs (independent of h) — overlaps the poll below
        float xg = 0.f;
        if (tid < 32) {
            const float* xr = xw + (size_t)pos * GATES + (tid >> 3) * 512 + hbase + (tid & 7);
            xg = __ldg(xr);
        }

        // per-warp gather: lane polls its warp's granule; sh slice is warp-private
        if (t == 0) {
            ((float2*)sh)[gran] = make_float2(0.f, 0.f);
        } else {
            const unsigned long long* src = &g_hx[dir][(t - 1) & 1][gran];
            float lo, hi;
            for (;;) {
                unsigned long long v = ld_rlx64(src);
                lo = __uint_as_float((unsigned)v);
                hi = __uint_as_float((unsigned)(v >> 32));
                if (fabsf(lo - coffc) <= WIN && fabsf(hi - coffc) <= WIN) break;
            }
            ((float2*)sh)[gran] = make_float2(lo - coffc, hi - coffc);
        }
        __syncwarp();      // warp-local: this warp's sh slice ready

        // matvec partial: register weights x warp-private smem h slice
        {
            const float* hv = sh + base;
            float a0 = 0.f, a1 = 0.f, a2 = 0.f, a3 = 0.f;
#pragma unroll
            for (int i = 0; i < 64; i += 4) {
                float4 h4 = *(const float4*)(hv + i);
                a0 = fmaf(w[i + 0], h4.x, a0);
                a1 = fmaf(w[i + 1], h4.y, a1);
                a2 = fmaf(w[i + 2], h4.z, a2);
                a3 = fmaf(w[i + 3], h4.w, a3);
            }
            zp[row * 9 + ck] = (a0 + a1) + (a2 + a3);
        }
        __syncthreads();   // zp ready (block-wide)

        // warp 0: gate-row sums + activations; 8 owners update state + publish
        if (tid < 32) {
            const float* zr = zp + tid * 9;
            float z = xg;
#pragma unroll
            for (int c = 0; c < 8; c++) z += zr[c];
            sact[tid] = ((tid >> 3) == 2) ? tanhap(z) : sigap(z);
        }
        __syncwarp();
        if (tid < 8) {
            float gi = sact[tid];
            float gf = sact[8 + tid];
            float gg = sact[16 + tid];
            float go_ = sact[24 + tid];
            c_state = gf * c_state + gi * gg;
            float h = go_ * tanhap(c_state);
            __stcg(hout + (size_t)pos * 1024 + (dir << 9) + hbase + tid, h);
            // publish: v = h + 4*(t%7), packed 2-per-b64, fire-and-forget
            float vv = h + coffp;
            float partner = __shfl_xor_sync(0x000000FFu, vv, 1);
            if ((tid & 1) == 0) {
                unsigned long long pk =
                    ((unsigned long long)__float_as_uint(partner) << 32) | __float_as_uint(vv);
                st_rlx64(&g_hx[dir][t & 1][j * 4 + (tid >> 1)], pk);
            }
        }
        kc = kp;
        kp = (kp == 6) ? 0 : kp + 1;
    }

    // exit/reset: make counters zero for the next launch / graph replay
    __syncthreads();
    if (tid == 0) {
        __threadfence();
        atomicAdd(&g_exit[dir][0], 1u);
        if (j == 0) {
            while (ld_acq(&g_exit[dir][0]) < (unsigned)RCTAS) { }
            g_cnt[dir][0] = 0u;
            __threadfence();
            atomicExch(&g_exit[dir][0], 0u);
        }
    }
}

// ---------------- pairwise MLP edge scores ----------------
__global__ void pair_score(const float* __restrict__ b1, const float* __restrict__ W2,
                           const float* __restrict__ b2) {
    __shared__ float Sh[32][101];
    __shared__ float Sm[32][101];
    __shared__ float sb1[MLPH], sw2[MLPH];
    int bh = blockIdx.y * 32, bm = blockIdx.x * 32;
    int tid = threadIdx.x;
    for (int i = tid; i < 32 * MLPH; i += 256) {
        int r = i / MLPH, c = i % MLPH;
        Sh[r][c] = g_sh[(size_t)(bh + r) * MLPH + c];
        Sm[r][c] = g_sm[(size_t)(bm + r) * MLPH + c];
    }
    if (tid < MLPH) { sb1[tid] = b1[tid]; sw2[tid] = W2[tid]; }
    __syncthreads();

    int tx = tid & 15, ty = tid >> 4;
    int h0 = ty * 2, m0 = tx * 2;
    float acc00 = 0.f, acc01 = 0.f, acc10 = 0.f, acc11 = 0.f;
    for (int jx = 0; jx < MLPH; jx++) {
        float w = sw2[jx], bb = sb1[jx];
        float a0 = Sh[h0][jx] + bb;
        float a1 = Sh[h0 + 1][jx] + bb;
        float c0 = Sm[m0][jx];
        float c1 = Sm[m0 + 1][jx];
        acc00 = fmaf(tanhap(a0 + c0), w, acc00);
        acc01 = fmaf(tanhap(a0 + c1), w, acc01);
        acc10 = fmaf(tanhap(a1 + c0), w, acc10);
        acc11 = fmaf(tanhap(a1 + c1), w, acc11);
    }
    float b2v = __ldg(b2);
    g_scores[(size_t)(bh + h0) * SEQ + bm + m0]         = acc00 + b2v;
    g_scores[(size_t)(bh + h0) * SEQ + bm + m0 + 1]     = acc01 + b2v;
    g_scores[(size_t)(bh + h0 + 1) * SEQ + bm + m0]     = acc10 + b2v;
    g_scores[(size_t)(bh + h0 + 1) * SEQ + bm + m0 + 1] = acc11 + b2v;
}

// ---------------- softmax over axis 0 ----------------
__global__ void softmax0(float* __restrict__ out) {
    int m = blockIdx.x;
    int tid = threadIdx.x;  // 128
    float v[4];
#pragma unroll
    for (int i = 0; i < 4; i++) v[i] = g_scores[(size_t)(tid + 128 * i) * SEQ + m];
    float mx = fmaxf(fmaxf(v[0], v[1]), fmaxf(v[2], v[3]));
    __shared__ float red[128];
    red[tid] = mx; __syncthreads();
    for (int o = 64; o > 0; o >>= 1) {
        if (tid < o) red[tid] = fmaxf(red[tid], red[tid + o]);
        __syncthreads();
    }
    mx = red[0]; __syncthreads();
    float e[4]; float ssum = 0.f;
#pragma unroll
    for (int i = 0; i < 4; i++) { e[i] = __expf(v[i] - mx); ssum += e[i]; }
    red[tid] = ssum; __syncthreads();
    for (int o = 64; o > 0; o >>= 1) {
        if (tid < o) red[tid] += red[tid + o];
        __syncthreads();
    }
    float inv = 1.f / red[0];
#pragma unroll
    for (int i = 0; i < 4; i++) out[(size_t)(tid + 128 * i) * SEQ + m] = e[i] * inv;
}

// ---------------- launch ----------------
extern "C" void kernel_launch(void* const* d_in, const int* in_sizes, int n_in,
                              void* d_out, int out_size) {
    const int*   wi  = (const int*)d_in[0];
    const int*   pi  = (const int*)d_in[1];
    const float* we  = (const float*)d_in[2];
    const float* pe  = (const float*)d_in[3];
    const float* wih0f = (const float*)d_in[4];
    const float* whh0f = (const float*)d_in[5];
    const float* b0f   = (const float*)d_in[6];
    const float* wih0b = (const float*)d_in[7];
    const float* whh0b = (const float*)d_in[8];
    const float* b0b   = (const float*)d_in[9];
    const float* wih1f = (const float*)d_in[10];
    const float* whh1f = (const float*)d_in[11];
    const float* b1f   = (const float*)d_in[12];
    const float* wih1b = (const float*)d_in[13];
    const float* whh1b = (const float*)d_in[14];
    const float* b1b   = (const float*)d_in[15];
    const float* W1    = (const float*)d_in[16];
    const float* b1    = (const float*)d_in[17];
    const float* W2    = (const float*)d_in[18];
    const float* b2    = (const float*)d_in[19];
    float* out = (float*)d_out;

    float *p_x0, *p_xw0, *p_xw1, *p_h0, *p_h1, *p_sh, *p_sm;
    cudaGetSymbolAddress((void**)&p_x0, g_x0);
    cudaGetSymbolAddress((void**)&p_xw0, g_xw0);
    cudaGetSymbolAddress((void**)&p_xw1, g_xw1);
    cudaGetSymbolAddress((void**)&p_h0, g_h0);
    cudaGetSymbolAddress((void**)&p_h1, g_h1);
    cudaGetSymbolAddress((void**)&p_sh, g_sh);
    cudaGetSymbolAddress((void**)&p_sm, g_sm);

    // 1. embeddings
    embed_kernel<<<SEQ, 256>>>(wi, pi, we, pe);

    // 2. layer0 input GEMMs (both directions in one launch, 128x64 tiles)
    {
        dim3 grid(GATES / 64, SEQ / 128, 2);
        gemm_big<<<grid, 256>>>(p_x0, IN0, wih0f, wih0b, IN0, b0f, b0b,
                                p_xw0, p_xw1, GATES, SEQ, GATES, IN0);
    }

    // 3. layer0 recurrence
    lstm_layer<<<2 * RCTAS, 256>>>(whh0f, whh0b, p_xw0, p_xw1, p_h0);

    // 4. layer1 input GEMMs (both directions in one launch, 128x64 tiles)
    {
        dim3 grid(GATES / 64, SEQ / 128, 2);
        gemm_big<<<grid, 256>>>(p_h0, IN1, wih1f, wih1b, IN1, b1f, b1b,
                                p_xw0, p_xw1, GATES, SEQ, GATES, IN1);
    }

    // 5. layer1 recurrence
    lstm_layer<<<2 * RCTAS, 256>>>(whh1f, whh1b, p_xw0, p_xw1, p_h1);

    // 6. MLP projections, both halves in one launch (W1 is [100, 2048] -> ldb = PAIRD)
    //    N=100 keeps the 64x64 kernel (128-wide tiles starved this gemm of CTAs in R10)
    {
        dim3 grid((MLPH + 63) / 64, SEQ / 64, 2);
        gemm_dual<<<grid, 256>>>(p_h1, 2 * HID, W1, W1 + 1024, PAIRD, nullptr, nullptr,
                                 p_sh, p_sm, MLPH, SEQ, MLPH, 2 * HID);
    }

    // 7. pairwise scores
    {
        dim3 grid(SEQ / 32, SEQ / 32);
        pair_score<<<grid, 256>>>(b1, W2, b2);
    }

    // 8. softmax over heads (axis 0)
    softmax0<<<SEQ, 128>>>(out);
}

// round 13
// speedup vs baseline: 1.2601x; 1.0684x over previous
#include <cuda_runtime.h>
#include <math.h>
#include <stdint.h>

#define SEQ   512
#define HID   512
#define IN0   1088
#define IN1   1024
#define GATES 2048
#define MLPH  100
#define PAIRD 2048
#define RCTAS 64   // CTAs per LSTM direction
#define WIN   1.5f

// ---------------- device scratch (no allocations allowed) ----------------
__device__ float g_x0[SEQ * IN0];
__device__ float g_xw0[SEQ * GATES];
__device__ float g_xw1[SEQ * GATES];
__device__ float g_h0[SEQ * 2 * HID];
__device__ float g_h1[SEQ * 2 * HID];
__device__ float g_sh[SEQ * MLPH];
__device__ float g_sm[SEQ * MLPH];
__device__ float g_scores[SEQ * SEQ];
// self-validating h exchange: [dir][buffer=t&1][granule 0..255] (8B = 2 h values)
__device__ __align__(128) unsigned long long g_hx[2][2][256];
__device__ __align__(128) unsigned g_cnt[2][32];    // one-time start barrier
__device__ __align__(128) unsigned g_exit[2][32];   // exit/reset barrier

// ---------------- helpers ----------------
__device__ __forceinline__ unsigned ld_acq(const unsigned* p) {
    unsigned v;
    asm volatile("ld.acquire.gpu.u32 %0, [%1];" : "=r"(v) : "l"(p) : "memory");
    return v;
}
__device__ __forceinline__ unsigned long long ld_rlx64(const unsigned long long* p) {
    unsigned long long v;
    asm volatile("ld.relaxed.gpu.global.b64 %0, [%1];" : "=l"(v) : "l"(p) : "memory");
    return v;
}
__device__ __forceinline__ void st_rlx64(unsigned long long* p, unsigned long long v) {
    asm volatile("st.relaxed.gpu.global.b64 [%0], %1;" :: "l"(p), "l"(v) : "memory");
}
__device__ __forceinline__ float tanhap(float x) {             // HW tanh
    float y;
    asm("tanh.approx.f32 %0, %1;" : "=f"(y) : "f"(x));
    return y;
}
__device__ __forceinline__ float sigap(float x) {              // sigmoid via HW tanh
    return fmaf(0.5f, tanhap(0.5f * x), 0.5f);
}
__device__ __forceinline__ uint32_t tf32cvt(float x) {         // f32 -> tf32 bits
    uint32_t u;
    asm("cvt.rna.tf32.f32 %0, %1;" : "=r"(u) : "f"(x));
    return u;
}
__device__ __forceinline__ void mma_tf32(float* d, const uint32_t* a, const uint32_t* b) {
    asm volatile(
        "mma.sync.aligned.m16n8k8.row.col.f32.tf32.tf32.f32 "
        "{%0,%1,%2,%3}, {%4,%5,%6,%7}, {%8,%9}, {%0,%1,%2,%3};"
        : "+f"(d[0]), "+f"(d[1]), "+f"(d[2]), "+f"(d[3])
        : "r"(a[0]), "r"(a[1]), "r"(a[2]), "r"(a[3]), "r"(b[0]), "r"(b[1]));
}

// ---------------- embeddings ----------------
__global__ void embed_kernel(const int* __restrict__ wi, const int* __restrict__ pi,
                             const float* __restrict__ we, const float* __restrict__ pe) {
    int t = blockIdx.x;
    int w = wi[t], p = pi[t];
    const float* wr = we + (size_t)w * 1024;
    const float* pr = pe + (size_t)p * 64;
    float* out = g_x0 + (size_t)t * IN0;
    for (int i = threadIdx.x; i < 1024; i += blockDim.x) out[i] = wr[i];
    for (int i = threadIdx.x; i < 64; i += blockDim.x) out[1024 + i] = pr[i];
}

// ---- big dual GEMM on tensor cores: C[M,N] = A[M,K] * B[N,K]^T (+bias), TF32 mma ----
// BM=128, BN=64, BK=16, 256 threads = 8 warps (warpM = wid&3 -> 32 rows,
// warpN = wid>>2 -> 32 cols). Per warp: 2 m16-tiles x 4 n8-tiles, K in k8 steps.
// As[k][row] stride 132, Bs[k][col] stride 68: frag gathers are bank-conflict-free
// (bank = 4*tig + gid). Requires M,N,K multiples of (any, 8, 16) at call sites used.
__global__ void __launch_bounds__(256, 1)
gemm_big(const float* __restrict__ A, int lda,
         const float* __restrict__ B0, const float* __restrict__ B1, int ldb,
         const float* __restrict__ bias0, const float* __restrict__ bias1,
         float* __restrict__ C0, float* __restrict__ C1, int ldc,
         int M, int N, int K) {
    const float* B = blockIdx.z ? B1 : B0;
    const float* bias = blockIdx.z ? bias1 : bias0;
    float* C = blockIdx.z ? C1 : C0;

    __shared__ __align__(16) float As[16][132];
    __shared__ __align__(16) float Bs[16][68];
    int bm = blockIdx.y * 128, bn = blockIdx.x * 64;
    int tid = threadIdx.x;
    int wid = tid >> 5, lane = tid & 31;
    int gid = lane >> 2, tig = lane & 3;
    int wm = (wid & 3) * 32;       // warp row offset in tile
    int wn = (wid >> 2) * 32;      // warp col offset in tile

    int lrA = tid >> 1;            // 0..127
    int lkA = (tid & 1) * 8;       // 0 or 8
    int lrB = tid >> 2;            // 0..63
    int lkB = (tid & 3) * 4;       // 0,4,8,12

    float acc[2][4][4];
#pragma unroll
    for (int mt = 0; mt < 2; mt++)
#pragma unroll
        for (int nt = 0; nt < 4; nt++)
#pragma unroll
            for (int r = 0; r < 4; r++) acc[mt][nt][r] = 0.f;

    int rowa = bm + lrA;
    int rowb = bn + lrB;
    bool a_ok = rowa < M;
    bool b_ok = rowb < N;

    // preload tile 0
    float4 va0 = make_float4(0.f, 0.f, 0.f, 0.f), va1 = va0, vb = va0;
    if (a_ok) {
        const float* p = A + (size_t)rowa * lda + lkA;
        va0 = *(const float4*)p; va1 = *(const float4*)(p + 4);
    }
    if (b_ok) vb = *(const float4*)(B + (size_t)rowb * ldb + lkB);

    for (int k0 = 0; k0 < K; k0 += 16) {
        As[lkA + 0][lrA] = va0.x; As[lkA + 1][lrA] = va0.y; As[lkA + 2][lrA] = va0.z; As[lkA + 3][lrA] = va0.w;
        As[lkA + 4][lrA] = va1.x; As[lkA + 5][lrA] = va1.y; As[lkA + 6][lrA] = va1.z; As[lkA + 7][lrA] = va1.w;
        Bs[lkB + 0][lrB] = vb.x; Bs[lkB + 1][lrB] = vb.y; Bs[lkB + 2][lrB] = vb.z; Bs[lkB + 3][lrB] = vb.w;
        __syncthreads();
        // prefetch next tile while computing
        if (k0 + 16 < K) {
            if (a_ok) {
                const float* p = A + (size_t)rowa * lda + k0 + 16 + lkA;
                va0 = *(const float4*)p; va1 = *(const float4*)(p + 4);
            }
            if (b_ok) vb = *(const float4*)(B + (size_t)rowb * ldb + k0 + 16 + lkB);
        }
#pragma unroll
        for (int ks = 0; ks < 2; ks++) {
            // A fragments: a0 (gid, tig), a1 (gid+8, tig), a2 (gid, tig+4), a3 (gid+8, tig+4)
            uint32_t afr[2][4];
#pragma unroll
            for (int mt = 0; mt < 2; mt++) {
                int r0 = wm + mt * 16 + gid;
                afr[mt][0] = tf32cvt(As[ks * 8 + tig][r0]);
                afr[mt][1] = tf32cvt(As[ks * 8 + tig][r0 + 8]);
                afr[mt][2] = tf32cvt(As[ks * 8 + 4 + tig][r0]);
                afr[mt][3] = tf32cvt(As[ks * 8 + 4 + tig][r0 + 8]);
            }
            // B fragments (col-major k8xn8): b0 (k=tig, n=gid), b1 (k=tig+4, n=gid)
            uint32_t bfr[4][2];
#pragma unroll
            for (int nt = 0; nt < 4; nt++) {
                int c0 = wn + nt * 8 + gid;
                bfr[nt][0] = tf32cvt(Bs[ks * 8 + tig][c0]);
                bfr[nt][1] = tf32cvt(Bs[ks * 8 + 4 + tig][c0]);
            }
#pragma unroll
            for (int mt = 0; mt < 2; mt++)
#pragma unroll
                for (int nt = 0; nt < 4; nt++)
                    mma_tf32(acc[mt][nt], afr[mt], bfr[nt]);
        }
        __syncthreads();
    }

    // epilogue: c0 (gid, 2tig), c1 (gid, 2tig+1), c2 (gid+8, 2tig), c3 (gid+8, 2tig+1)
#pragma unroll
    for (int mt = 0; mt < 2; mt++) {
#pragma unroll
        for (int nt = 0; nt < 4; nt++) {
            int r = bm + wm + mt * 16 + gid;
            int c = bn + wn + nt * 8 + 2 * tig;
            float bv0 = bias ? bias[c] : 0.f;
            float bv1 = bias ? bias[c + 1] : 0.f;
            if (r < M && c < N) {
                C[(size_t)r * ldc + c]     = acc[mt][nt][0] + bv0;
                C[(size_t)r * ldc + c + 1] = acc[mt][nt][1] + bv1;
            }
            if (r + 8 < M && c < N) {
                C[(size_t)(r + 8) * ldc + c]     = acc[mt][nt][2] + bv0;
                C[(size_t)(r + 8) * ldc + c + 1] = acc[mt][nt][3] + bv1;
            }
        }
    }
}

// ---- dual GEMM: BM=64, BN=64, BK=16, 256 threads, 4x4 tile (fp32; N=100 MLP) ----
__global__ void gemm_dual(const float* __restrict__ A, int lda,
                          const float* __restrict__ B0, const float* __restrict__ B1, int ldb,
                          const float* __restrict__ bias0, const float* __restrict__ bias1,
                          float* __restrict__ C0, float* __restrict__ C1, int ldc,
                          int M, int N, int K) {
    const float* B = blockIdx.z ? B1 : B0;
    const float* bias = blockIdx.z ? bias1 : bias0;
    float* C = blockIdx.z ? C1 : C0;

    __shared__ __align__(16) float As[16][68];
    __shared__ __align__(16) float Bs[16][68];
    int bm = blockIdx.y * 64, bn = blockIdx.x * 64;
    int tid = threadIdx.x;
    int tx = tid & 15, ty = tid >> 4;
    int lr = tid >> 2;
    int lk = (tid & 3) * 4;

    float acc[4][4];
#pragma unroll
    for (int i = 0; i < 4; i++)
#pragma unroll
        for (int j = 0; j < 4; j++) acc[i][j] = 0.f;

    int rowa = bm + lr;
    int rowb = bn + lr;

    float4 va = make_float4(0.f, 0.f, 0.f, 0.f);
    float4 vb = make_float4(0.f, 0.f, 0.f, 0.f);
    if (rowa < M) va = *(const float4*)(A + (size_t)rowa * lda + lk);
    if (rowb < N) vb = *(const float4*)(B + (size_t)rowb * ldb + lk);

    for (int k0 = 0; k0 < K; k0 += 16) {
        As[lk + 0][lr] = va.x; As[lk + 1][lr] = va.y; As[lk + 2][lr] = va.z; As[lk + 3][lr] = va.w;
        Bs[lk + 0][lr] = vb.x; Bs[lk + 1][lr] = vb.y; Bs[lk + 2][lr] = vb.z; Bs[lk + 3][lr] = vb.w;
        __syncthreads();
        if (k0 + 16 < K) {
            va = make_float4(0.f, 0.f, 0.f, 0.f);
            vb = make_float4(0.f, 0.f, 0.f, 0.f);
            if (rowa < M) va = *(const float4*)(A + (size_t)rowa * lda + k0 + 16 + lk);
            if (rowb < N) vb = *(const float4*)(B + (size_t)rowb * ldb + k0 + 16 + lk);
        }
#pragma unroll
        for (int k = 0; k < 16; k++) {
            float4 a4 = *(const float4*)&As[k][ty * 4];
            float4 b4 = *(const float4*)&Bs[k][tx * 4];
            float a[4] = {a4.x, a4.y, a4.z, a4.w};
            float b[4] = {b4.x, b4.y, b4.z, b4.w};
#pragma unroll
            for (int i = 0; i < 4; i++)
#pragma unroll
                for (int j = 0; j < 4; j++) acc[i][j] = fmaf(a[i], b[j], acc[i][j]);
        }
        __syncthreads();
    }
#pragma unroll
    for (int i = 0; i < 4; i++) {
        int r = bm + ty * 4 + i;
        if (r >= M) continue;
#pragma unroll
        for (int j = 0; j < 4; j++) {
            int c = bn + tx * 4 + j;
            if (c < N) C[(size_t)r * ldc + c] = acc[i][j] + (bias ? bias[c] : 0.f);
        }
    }
}

// ---------------- LSTM recurrence: warp-private h slices + self-validating exchange -----
// (R11-winning structure — protected, unchanged)
__global__ void __launch_bounds__(256, 1)
lstm_layer(const float* __restrict__ whh_f, const float* __restrict__ whh_b,
           const float* __restrict__ xw_f, const float* __restrict__ xw_b,
           float* __restrict__ hout) {
    __shared__ float sh[512];
    __shared__ float zp[32 * 9];
    __shared__ float sact[32];

    int dir = blockIdx.x >> 6;
    int j = blockIdx.x & 63;
    int hbase = j * 8;
    const float* W = dir ? whh_b : whh_f;
    const float* xw = dir ? xw_b : xw_f;
    int tid = threadIdx.x;
    int lane = tid & 31;

    int row = tid & 31;            // gate row within CTA (0..31)
    int ck = tid >> 5;             // K chunk == warp id (0..7)
    const int base = ck * 64;

    // weights into registers
    float w[64];
    {
        const float* src = W + (size_t)((row >> 3) * 512 + hbase + (row & 7)) * 512 + base;
#pragma unroll
        for (int i = 0; i < 64; i += 4) {
            float4 v = *(const float4*)(src + i);
            w[i] = v.x; w[i + 1] = v.y; w[i + 2] = v.z; w[i + 3] = v.w;
        }
    }

    // one-time: poison own hx granules, then grid start-barrier (per direction)
    if (tid == 0) {
        unsigned long long poison =
            ((unsigned long long)__float_as_uint(1e30f) << 32) | __float_as_uint(1e30f);
#pragma unroll
        for (int b = 0; b < 2; b++)
#pragma unroll
            for (int q = 0; q < 4; q++)
                st_rlx64(&g_hx[dir][b][j * 4 + q], poison);
        __threadfence();
        atomicAdd(&g_cnt[dir][0], 1u);
        while (ld_acq(&g_cnt[dir][0]) < (unsigned)RCTAS) { }
    }
    __syncthreads();

    float c_state = 0.f;           // owned by threads 0..7
    int kp = 0, kc = 0;            // t mod 7 (producer), (t-1) mod 7 (consumer)
    const int gran = ck * 32 + lane;   // this lane's granule (warp-private slice)

    for (int t = 0; t < 512; t++) {
        int pos = dir ? (511 - t) : t;
        float coffp = 4.0f * (float)kp;
        float coffc = 4.0f * (float)kc;

        // prefetch gate inputs (independent of h) — overlaps the poll below
        float xg = 0.f;
        if (tid < 32) {
            const float* xr = xw + (size_t)pos * GATES + (tid >> 3) * 512 + hbase + (tid & 7);
            xg = __ldg(xr);
        }

        // per-warp gather: lane polls its warp's granule; sh slice is warp-private
        if (t == 0) {
            ((float2*)sh)[gran] = make_float2(0.f, 0.f);
        } else {
            const unsigned long long* src = &g_hx[dir][(t - 1) & 1][gran];
            float lo, hi;
            for (;;) {
                unsigned long long v = ld_rlx64(src);
                lo = __uint_as_float((unsigned)v);
                hi = __uint_as_float((unsigned)(v >> 32));
                if (fabsf(lo - coffc) <= WIN && fabsf(hi - coffc) <= WIN) break;
            }
            ((float2*)sh)[gran] = make_float2(lo - coffc, hi - coffc);
        }
        __syncwarp();      // warp-local: this warp's sh slice ready

        // matvec partial: register weights x warp-private smem h slice
        {
            const float* hv = sh + base;
            float a0 = 0.f, a1 = 0.f, a2 = 0.f, a3 = 0.f;
#pragma unroll
            for (int i = 0; i < 64; i += 4) {
                float4 h4 = *(const float4*)(hv + i);
                a0 = fmaf(w[i + 0], h4.x, a0);
                a1 = fmaf(w[i + 1], h4.y, a1);
                a2 = fmaf(w[i + 2], h4.z, a2);
                a3 = fmaf(w[i + 3], h4.w, a3);
            }
            zp[row * 9 + ck] = (a0 + a1) + (a2 + a3);
        }
        __syncthreads();   // zp ready (block-wide)

        // warp 0: gate-row sums + activations; 8 owners update state + publish
        if (tid < 32) {
            const float* zr = zp + tid * 9;
            float z = xg;
#pragma unroll
            for (int c = 0; c < 8; c++) z += zr[c];
            sact[tid] = ((tid >> 3) == 2) ? tanhap(z) : sigap(z);
        }
        __syncwarp();
        if (tid < 8) {
            float gi = sact[tid];
            float gf = sact[8 + tid];
            float gg = sact[16 + tid];
            float go_ = sact[24 + tid];
            c_state = gf * c_state + gi * gg;
            float h = go_ * tanhap(c_state);
            __stcg(hout + (size_t)pos * 1024 + (dir << 9) + hbase + tid, h);
            // publish: v = h + 4*(t%7), packed 2-per-b64, fire-and-forget
            float vv = h + coffp;
            float partner = __shfl_xor_sync(0x000000FFu, vv, 1);
            if ((tid & 1) == 0) {
                unsigned long long pk =
                    ((unsigned long long)__float_as_uint(partner) << 32) | __float_as_uint(vv);
                st_rlx64(&g_hx[dir][t & 1][j * 4 + (tid >> 1)], pk);
            }
        }
        kc = kp;
        kp = (kp == 6) ? 0 : kp + 1;
    }

    // exit/reset: make counters zero for the next launch / graph replay
    __syncthreads();
    if (tid == 0) {
        __threadfence();
        atomicAdd(&g_exit[dir][0], 1u);
        if (j == 0) {
            while (ld_acq(&g_exit[dir][0]) < (unsigned)RCTAS) { }
            g_cnt[dir][0] = 0u;
            __threadfence();
            atomicExch(&g_exit[dir][0], 0u);
        }
    }
}

// ---------------- pairwise MLP edge scores ----------------
__global__ void pair_score(const float* __restrict__ b1, const float* __restrict__ W2,
                           const float* __restrict__ b2) {
    __shared__ float Sh[32][101];
    __shared__ float Sm[32][101];
    __shared__ float sb1[MLPH], sw2[MLPH];
    int bh = blockIdx.y * 32, bm = blockIdx.x * 32;
    int tid = threadIdx.x;
    for (int i = tid; i < 32 * MLPH; i += 256) {
        int r = i / MLPH, c = i % MLPH;
        Sh[r][c] = g_sh[(size_t)(bh + r) * MLPH + c];
        Sm[r][c] = g_sm[(size_t)(bm + r) * MLPH + c];
    }
    if (tid < MLPH) { sb1[tid] = b1[tid]; sw2[tid] = W2[tid]; }
    __syncthreads();

    int tx = tid & 15, ty = tid >> 4;
    int h0 = ty * 2, m0 = tx * 2;
    float acc00 = 0.f, acc01 = 0.f, acc10 = 0.f, acc11 = 0.f;
    for (int jx = 0; jx < MLPH; jx++) {
        float w = sw2[jx], bb = sb1[jx];
        float a0 = Sh[h0][jx] + bb;
        float a1 = Sh[h0 + 1][jx] + bb;
        float c0 = Sm[m0][jx];
        float c1 = Sm[m0 + 1][jx];
        acc00 = fmaf(tanhap(a0 + c0), w, acc00);
        acc01 = fmaf(tanhap(a0 + c1), w, acc01);
        acc10 = fmaf(tanhap(a1 + c0), w, acc10);
        acc11 = fmaf(tanhap(a1 + c1), w, acc11);
    }
    float b2v = __ldg(b2);
    g_scores[(size_t)(bh + h0) * SEQ + bm + m0]         = acc00 + b2v;
    g_scores[(size_t)(bh + h0) * SEQ + bm + m0 + 1]     = acc01 + b2v;
    g_scores[(size_t)(bh + h0 + 1) * SEQ + bm + m0]     = acc10 + b2v;
    g_scores[(size_t)(bh + h0 + 1) * SEQ + bm + m0 + 1] = acc11 + b2v;
}

// ---------------- softmax over axis 0 ----------------
__global__ void softmax0(float* __restrict__ out) {
    int m = blockIdx.x;
    int tid = threadIdx.x;  // 128
    float v[4];
#pragma unroll
    for (int i = 0; i < 4; i++) v[i] = g_scores[(size_t)(tid + 128 * i) * SEQ + m];
    float mx = fmaxf(fmaxf(v[0], v[1]), fmaxf(v[2], v[3]));
    __shared__ float red[128];
    red[tid] = mx; __syncthreads();
    for (int o = 64; o > 0; o >>= 1) {
        if (tid < o) red[tid] = fmaxf(red[tid], red[tid + o]);
        __syncthreads();
    }
    mx = red[0]; __syncthreads();
    float e[4]; float ssum = 0.f;
#pragma unroll
    for (int i = 0; i < 4; i++) { e[i] = __expf(v[i] - mx); ssum += e[i]; }
    red[tid] = ssum; __syncthreads();
    for (int o = 64; o > 0; o >>= 1) {
        if (tid < o) red[tid] += red[tid + o];
        __syncthreads();
    }
    float inv = 1.f / red[0];
#pragma unroll
    for (int i = 0; i < 4; i++) out[(size_t)(tid + 128 * i) * SEQ + m] = e[i] * inv;
}

// ---------------- launch ----------------
extern "C" void kernel_launch(void* const* d_in, const int* in_sizes, int n_in,
                              void* d_out, int out_size) {
    const int*   wi  = (const int*)d_in[0];
    const int*   pi  = (const int*)d_in[1];
    const float* we  = (const float*)d_in[2];
    const float* pe  = (const float*)d_in[3];
    const float* wih0f = (const float*)d_in[4];
    const float* whh0f = (const float*)d_in[5];
    const float* b0f   = (const float*)d_in[6];
    const float* wih0b = (const float*)d_in[7];
    const float* whh0b = (const float*)d_in[8];
    const float* b0b   = (const float*)d_in[9];
    const float* wih1f = (const float*)d_in[10];
    const float* whh1f = (const float*)d_in[11];
    const float* b1f   = (const float*)d_in[12];
    const float* wih1b = (const float*)d_in[13];
    const float* whh1b = (const float*)d_in[14];
    const float* b1b   = (const float*)d_in[15];
    const float* W1    = (const float*)d_in[16];
    const float* b1    = (const float*)d_in[17];
    const float* W2    = (const float*)d_in[18];
    const float* b2    = (const float*)d_in[19];
    float* out = (float*)d_out;

    float *p_x0, *p_xw0, *p_xw1, *p_h0, *p_h1, *p_sh, *p_sm;
    cudaGetSymbolAddress((void**)&p_x0, g_x0);
    cudaGetSymbolAddress((void**)&p_xw0, g_xw0);
    cudaGetSymbolAddress((void**)&p_xw1, g_xw1);
    cudaGetSymbolAddress((void**)&p_h0, g_h0);
    cudaGetSymbolAddress((void**)&p_h1, g_h1);
    cudaGetSymbolAddress((void**)&p_sh, g_sh);
    cudaGetSymbolAddress((void**)&p_sm, g_sm);

    // 1. embeddings
    embed_kernel<<<SEQ, 256>>>(wi, pi, we, pe);

    // 2. layer0 input GEMMs (both directions in one launch, TF32 tensor cores)
    {
        dim3 grid(GATES / 64, SEQ / 128, 2);
        gemm_big<<<grid, 256>>>(p_x0, IN0, wih0f, wih0b, IN0, b0f, b0b,
                                p_xw0, p_xw1, GATES, SEQ, GATES, IN0);
    }

    // 3. layer0 recurrence
    lstm_layer<<<2 * RCTAS, 256>>>(whh0f, whh0b, p_xw0, p_xw1, p_h0);

    // 4. layer1 input GEMMs (both directions in one launch, TF32 tensor cores)
    {
        dim3 grid(GATES / 64, SEQ / 128, 2);
        gemm_big<<<grid, 256>>>(p_h0, IN1, wih1f, wih1b, IN1, b1f, b1b,
                                p_xw0, p_xw1, GATES, SEQ, GATES, IN1);
    }

    // 5. layer1 recurrence
    lstm_layer<<<2 * RCTAS, 256>>>(whh1f, whh1b, p_xw0, p_xw1, p_h1);

    // 6. MLP projections, both halves in one launch (W1 is [100, 2048] -> ldb = PAIRD)
    //    fp32 path (N=100; tensor tiles would starve it of CTAs)
    {
        dim3 grid((MLPH + 63) / 64, SEQ / 64, 2);
        gemm_dual<<<grid, 256>>>(p_h1, 2 * HID, W1, W1 + 1024, PAIRD, nullptr, nullptr,
                                 p_sh, p_sm, MLPH, SEQ, MLPH, 2 * HID);
    }

    // 7. pairwise scores
    {
        dim3 grid(SEQ / 32, SEQ / 32);
        pair_score<<<grid, 256>>>(b1, W2, b2);
    }

    // 8. softmax over heads (axis 0)
    softmax0<<<SEQ, 128>>>(out);
}

// round 14
// speedup vs baseline: 1.2601x; 1.0000x over previous
#include <cuda_runtime.h>
#include <math.h>
#include <stdint.h>

#define SEQ   512
#define HID   512
#define IN0   1088
#define IN1   1024
#define GATES 2048
#define MLPH  100
#define PAIRD 2048
#define RCTAS 64   // CTAs per LSTM direction
#define WIN   1.5f

// ---------------- device scratch (no allocations allowed) ----------------
__device__ float g_x0[SEQ * IN0];
__device__ float g_xw0[SEQ * GATES];
__device__ float g_xw1[SEQ * GATES];
__device__ float g_h0[SEQ * 2 * HID];
__device__ float g_h1[SEQ * 2 * HID];
__device__ float g_sh[SEQ * MLPH];
__device__ float g_sm[SEQ * MLPH];
__device__ float g_scores[SEQ * SEQ];
// self-validating h exchange: [dir][buffer=t&1][granule 0..255] (8B = 2 h values)
__device__ __align__(128) unsigned long long g_hx[2][2][256];
__device__ __align__(128) unsigned g_cnt[2][32];    // one-time start barrier
__device__ __align__(128) unsigned g_exit[2][32];   // exit/reset barrier

// ---------------- helpers ----------------
__device__ __forceinline__ unsigned ld_acq(const unsigned* p) {
    unsigned v;
    asm volatile("ld.acquire.gpu.u32 %0, [%1];" : "=r"(v) : "l"(p) : "memory");
    return v;
}
__device__ __forceinline__ unsigned long long ld_rlx64(const unsigned long long* p) {
    unsigned long long v;
    asm volatile("ld.relaxed.gpu.global.b64 %0, [%1];" : "=l"(v) : "l"(p) : "memory");
    return v;
}
__device__ __forceinline__ void st_rlx64(unsigned long long* p, unsigned long long v) {
    asm volatile("st.relaxed.gpu.global.b64 [%0], %1;" :: "l"(p), "l"(v) : "memory");
}
__device__ __forceinline__ float tanhap(float x) {             // HW tanh
    float y;
    asm("tanh.approx.f32 %0, %1;" : "=f"(y) : "f"(x));
    return y;
}
__device__ __forceinline__ float sigap(float x) {              // sigmoid via HW tanh
    return fmaf(0.5f, tanhap(0.5f * x), 0.5f);
}
__device__ __forceinline__ uint32_t tf32cvt(float x) {         // f32 -> tf32 bits
    uint32_t u;
    asm("cvt.rna.tf32.f32 %0, %1;" : "=r"(u) : "f"(x));
    return u;
}
__device__ __forceinline__ void mma_tf32(float* d, const uint32_t* a, const uint32_t* b) {
    asm volatile(
        "mma.sync.aligned.m16n8k8.row.col.f32.tf32.tf32.f32 "
        "{%0,%1,%2,%3}, {%4,%5,%6,%7}, {%8,%9}, {%0,%1,%2,%3};"
        : "+f"(d[0]), "+f"(d[1]), "+f"(d[2]), "+f"(d[3])
        : "r"(a[0]), "r"(a[1]), "r"(a[2]), "r"(a[3]), "r"(b[0]), "r"(b[1]));
}

// ---------------- embeddings ----------------
__global__ void embed_kernel(const int* __restrict__ wi, const int* __restrict__ pi,
                             const float* __restrict__ we, const float* __restrict__ pe) {
    int t = blockIdx.x;
    int w = wi[t], p = pi[t];
    const float* wr = we + (size_t)w * 1024;
    const float* pr = pe + (size_t)p * 64;
    float* out = g_x0 + (size_t)t * IN0;
    for (int i = threadIdx.x; i < 1024; i += blockDim.x) out[i] = wr[i];
    for (int i = threadIdx.x; i < 64; i += blockDim.x) out[1024 + i] = pr[i];
}

// ---- big dual GEMM on tensor cores: C[M,N] = A[M,K] * B[N,K]^T (+bias), TF32 mma ----
// BM=128, BN=64, BK=16, 256 threads = 8 warps. Smem holds PRE-CONVERTED tf32 bits
// (cvt once at store; frag gather is plain LDS.32). Double-buffered: one sync/tile.
__global__ void __launch_bounds__(256, 1)
gemm_big(const float* __restrict__ A, int lda,
         const float* __restrict__ B0, const float* __restrict__ B1, int ldb,
         const float* __restrict__ bias0, const float* __restrict__ bias1,
         float* __restrict__ C0, float* __restrict__ C1, int ldc,
         int M, int N, int K) {
    const float* B = blockIdx.z ? B1 : B0;
    const float* bias = blockIdx.z ? bias1 : bias0;
    float* C = blockIdx.z ? C1 : C0;

    __shared__ __align__(16) uint32_t As[2][16][132];
    __shared__ __align__(16) uint32_t Bs[2][16][68];
    int bm = blockIdx.y * 128, bn = blockIdx.x * 64;
    int tid = threadIdx.x;
    int wid = tid >> 5, lane = tid & 31;
    int gid = lane >> 2, tig = lane & 3;
    int wm = (wid & 3) * 32;       // warp row offset in tile
    int wn = (wid >> 2) * 32;      // warp col offset in tile

    int lrA = tid >> 1;            // 0..127
    int lkA = (tid & 1) * 8;       // 0 or 8
    int lrB = tid >> 2;            // 0..63
    int lkB = (tid & 3) * 4;       // 0,4,8,12

    float acc[2][4][4];
#pragma unroll
    for (int mt = 0; mt < 2; mt++)
#pragma unroll
        for (int nt = 0; nt < 4; nt++)
#pragma unroll
            for (int r = 0; r < 4; r++) acc[mt][nt][r] = 0.f;

    int rowa = bm + lrA;
    int rowb = bn + lrB;
    bool a_ok = rowa < M;
    bool b_ok = rowb < N;

    // preload + store tile 0 into buffer 0
    float4 va0 = make_float4(0.f, 0.f, 0.f, 0.f), va1 = va0, vb = va0;
    if (a_ok) {
        const float* p = A + (size_t)rowa * lda;
        va0 = *(const float4*)(p + lkA); va1 = *(const float4*)(p + lkA + 4);
    }
    if (b_ok) vb = *(const float4*)(B + (size_t)rowb * ldb + lkB);
    As[0][lkA + 0][lrA] = tf32cvt(va0.x); As[0][lkA + 1][lrA] = tf32cvt(va0.y);
    As[0][lkA + 2][lrA] = tf32cvt(va0.z); As[0][lkA + 3][lrA] = tf32cvt(va0.w);
    As[0][lkA + 4][lrA] = tf32cvt(va1.x); As[0][lkA + 5][lrA] = tf32cvt(va1.y);
    As[0][lkA + 6][lrA] = tf32cvt(va1.z); As[0][lkA + 7][lrA] = tf32cvt(va1.w);
    Bs[0][lkB + 0][lrB] = tf32cvt(vb.x); Bs[0][lkB + 1][lrB] = tf32cvt(vb.y);
    Bs[0][lkB + 2][lrB] = tf32cvt(vb.z); Bs[0][lkB + 3][lrB] = tf32cvt(vb.w);
    __syncthreads();

    int cur = 0;
    for (int k0 = 0; k0 < K; k0 += 16) {
        bool has_next = (k0 + 16) < K;
        // issue global loads for the next tile (overlap with compute below)
        if (has_next) {
            if (a_ok) {
                const float* p = A + (size_t)rowa * lda + k0 + 16;
                va0 = *(const float4*)(p + lkA); va1 = *(const float4*)(p + lkA + 4);
            }
            if (b_ok) vb = *(const float4*)(B + (size_t)rowb * ldb + k0 + 16 + lkB);
        }
        // compute from buffer cur (frags are plain u32 loads, no cvt)
#pragma unroll
        for (int ks = 0; ks < 2; ks++) {
            uint32_t afr[2][4];
#pragma unroll
            for (int mt = 0; mt < 2; mt++) {
                int r0 = wm + mt * 16 + gid;
                afr[mt][0] = As[cur][ks * 8 + tig][r0];
                afr[mt][1] = As[cur][ks * 8 + tig][r0 + 8];
                afr[mt][2] = As[cur][ks * 8 + 4 + tig][r0];
                afr[mt][3] = As[cur][ks * 8 + 4 + tig][r0 + 8];
            }
            uint32_t bfr[4][2];
#pragma unroll
            for (int nt = 0; nt < 4; nt++) {
                int c0 = wn + nt * 8 + gid;
                bfr[nt][0] = Bs[cur][ks * 8 + tig][c0];
                bfr[nt][1] = Bs[cur][ks * 8 + 4 + tig][c0];
            }
#pragma unroll
            for (int mt = 0; mt < 2; mt++)
#pragma unroll
                for (int nt = 0; nt < 4; nt++)
                    mma_tf32(acc[mt][nt], afr[mt], bfr[nt]);
        }
        // store next tile into the other buffer, single sync, swap
        if (has_next) {
            int nxt = cur ^ 1;
            As[nxt][lkA + 0][lrA] = tf32cvt(va0.x); As[nxt][lkA + 1][lrA] = tf32cvt(va0.y);
            As[nxt][lkA + 2][lrA] = tf32cvt(va0.z); As[nxt][lkA + 3][lrA] = tf32cvt(va0.w);
            As[nxt][lkA + 4][lrA] = tf32cvt(va1.x); As[nxt][lkA + 5][lrA] = tf32cvt(va1.y);
            As[nxt][lkA + 6][lrA] = tf32cvt(va1.z); As[nxt][lkA + 7][lrA] = tf32cvt(va1.w);
            Bs[nxt][lkB + 0][lrB] = tf32cvt(vb.x); Bs[nxt][lkB + 1][lrB] = tf32cvt(vb.y);
            Bs[nxt][lkB + 2][lrB] = tf32cvt(vb.z); Bs[nxt][lkB + 3][lrB] = tf32cvt(vb.w);
            __syncthreads();
            cur = nxt;
        }
    }

    // epilogue: c0 (gid, 2tig), c1 (gid, 2tig+1), c2 (gid+8, 2tig), c3 (gid+8, 2tig+1)
#pragma unroll
    for (int mt = 0; mt < 2; mt++) {
#pragma unroll
        for (int nt = 0; nt < 4; nt++) {
            int r = bm + wm + mt * 16 + gid;
            int c = bn + wn + nt * 8 + 2 * tig;
            float bv0 = bias ? bias[c] : 0.f;
            float bv1 = bias ? bias[c + 1] : 0.f;
            if (r < M && c < N) {
                C[(size_t)r * ldc + c]     = acc[mt][nt][0] + bv0;
                C[(size_t)r * ldc + c + 1] = acc[mt][nt][1] + bv1;
            }
            if (r + 8 < M && c < N) {
                C[(size_t)(r + 8) * ldc + c]     = acc[mt][nt][2] + bv0;
                C[(size_t)(r + 8) * ldc + c + 1] = acc[mt][nt][3] + bv1;
            }
        }
    }
}

// ---- dual GEMM: BM=64, BN=64, BK=16, 256 threads, 4x4 tile (fp32; N=100 MLP) ----
__global__ void gemm_dual(const float* __restrict__ A, int lda,
                          const float* __restrict__ B0, const float* __restrict__ B1, int ldb,
                          const float* __restrict__ bias0, const float* __restrict__ bias1,
                          float* __restrict__ C0, float* __restrict__ C1, int ldc,
                          int M, int N, int K) {
    const float* B = blockIdx.z ? B1 : B0;
    const float* bias = blockIdx.z ? bias1 : bias0;
    float* C = blockIdx.z ? C1 : C0;

    __shared__ __align__(16) float As[16][68];
    __shared__ __align__(16) float Bs[16][68];
    int bm = blockIdx.y * 64, bn = blockIdx.x * 64;
    int tid = threadIdx.x;
    int tx = tid & 15, ty = tid >> 4;
    int lr = tid >> 2;
    int lk = (tid & 3) * 4;

    float acc[4][4];
#pragma unroll
    for (int i = 0; i < 4; i++)
#pragma unroll
        for (int j = 0; j < 4; j++) acc[i][j] = 0.f;

    int rowa = bm + lr;
    int rowb = bn + lr;

    float4 va = make_float4(0.f, 0.f, 0.f, 0.f);
    float4 vb = make_float4(0.f, 0.f, 0.f, 0.f);
    if (rowa < M) va = *(const float4*)(A + (size_t)rowa * lda + lk);
    if (rowb < N) vb = *(const float4*)(B + (size_t)rowb * ldb + lk);

    for (int k0 = 0; k0 < K; k0 += 16) {
        As[lk + 0][lr] = va.x; As[lk + 1][lr] = va.y; As[lk + 2][lr] = va.z; As[lk + 3][lr] = va.w;
        Bs[lk + 0][lr] = vb.x; Bs[lk + 1][lr] = vb.y; Bs[lk + 2][lr] = vb.z; Bs[lk + 3][lr] = vb.w;
        __syncthreads();
        if (k0 + 16 < K) {
            va = make_float4(0.f, 0.f, 0.f, 0.f);
            vb = make_float4(0.f, 0.f, 0.f, 0.f);
            if (rowa < M) va = *(const float4*)(A + (size_t)rowa * lda + k0 + 16 + lk);
            if (rowb < N) vb = *(const float4*)(B + (size_t)rowb * ldb + k0 + 16 + lk);
        }
#pragma unroll
        for (int k = 0; k < 16; k++) {
            float4 a4 = *(const float4*)&As[k][ty * 4];
            float4 b4 = *(const float4*)&Bs[k][tx * 4];
            float a[4] = {a4.x, a4.y, a4.z, a4.w};
            float b[4] = {b4.x, b4.y, b4.z, b4.w};
#pragma unroll
            for (int i = 0; i < 4; i++)
#pragma unroll
                for (int j = 0; j < 4; j++) acc[i][j] = fmaf(a[i], b[j], acc[i][j]);
        }
        __syncthreads();
    }
#pragma unroll
    for (int i = 0; i < 4; i++) {
        int r = bm + ty * 4 + i;
        if (r >= M) continue;
#pragma unroll
        for (int j = 0; j < 4; j++) {
            int c = bn + tx * 4 + j;
            if (c < N) C[(size_t)r * ldc + c] = acc[i][j] + (bias ? bias[c] : 0.f);
        }
    }
}

// ---------------- LSTM recurrence: warp-private h slices + self-validating exchange -----
// (R11-winning structure — protected; only change: publish granule BEFORE hout store)
__global__ void __launch_bounds__(256, 1)
lstm_layer(const float* __restrict__ whh_f, const float* __restrict__ whh_b,
           const float* __restrict__ xw_f, const float* __restrict__ xw_b,
           float* __restrict__ hout) {
    __shared__ float sh[512];
    __shared__ float zp[32 * 9];
    __shared__ float sact[32];

    int dir = blockIdx.x >> 6;
    int j = blockIdx.x & 63;
    int hbase = j * 8;
    const float* W = dir ? whh_b : whh_f;
    const float* xw = dir ? xw_b : xw_f;
    int tid = threadIdx.x;
    int lane = tid & 31;

    int row = tid & 31;            // gate row within CTA (0..31)
    int ck = tid >> 5;             // K chunk == warp id (0..7)
    const int base = ck * 64;

    // weights into registers
    float w[64];
    {
        const float* src = W + (size_t)((row >> 3) * 512 + hbase + (row & 7)) * 512 + base;
#pragma unroll
        for (int i = 0; i < 64; i += 4) {
            float4 v = *(const float4*)(src + i);
            w[i] = v.x; w[i + 1] = v.y; w[i + 2] = v.z; w[i + 3] = v.w;
        }
    }

    // one-time: poison own hx granules, then grid start-barrier (per direction)
    if (tid == 0) {
        unsigned long long poison =
            ((unsigned long long)__float_as_uint(1e30f) << 32) | __float_as_uint(1e30f);
#pragma unroll
        for (int b = 0; b < 2; b++)
#pragma unroll
            for (int q = 0; q < 4; q++)
                st_rlx64(&g_hx[dir][b][j * 4 + q], poison);
        __threadfence();
        atomicAdd(&g_cnt[dir][0], 1u);
        while (ld_acq(&g_cnt[dir][0]) < (unsigned)RCTAS) { }
    }
    __syncthreads();

    float c_state = 0.f;           // owned by threads 0..7
    int kp = 0, kc = 0;            // t mod 7 (producer), (t-1) mod 7 (consumer)
    const int gran = ck * 32 + lane;   // this lane's granule (warp-private slice)

    for (int t = 0; t < 512; t++) {
        int pos = dir ? (511 - t) : t;
        float coffp = 4.0f * (float)kp;
        float coffc = 4.0f * (float)kc;

        // prefetch gate inputs (independent of h) — overlaps the poll below
        float xg = 0.f;
        if (tid < 32) {
            const float* xr = xw + (size_t)pos * GATES + (tid >> 3) * 512 + hbase + (tid & 7);
            xg = __ldg(xr);
        }

        // per-warp gather: lane polls its warp's granule; sh slice is warp-private
        if (t == 0) {
            ((float2*)sh)[gran] = make_float2(0.f, 0.f);
        } else {
            const unsigned long long* src = &g_hx[dir][(t - 1) & 1][gran];
            float lo, hi;
            for (;;) {
                unsigned long long v = ld_rlx64(src);
                lo = __uint_as_float((unsigned)v);
                hi = __uint_as_float((unsigned)(v >> 32));
                if (fabsf(lo - coffc) <= WIN && fabsf(hi - coffc) <= WIN) break;
            }
            ((float2*)sh)[gran] = make_float2(lo - coffc, hi - coffc);
        }
        __syncwarp();      // warp-local: this warp's sh slice ready

        // matvec partial: register weights x warp-private smem h slice
        {
            const float* hv = sh + base;
            float a0 = 0.f, a1 = 0.f, a2 = 0.f, a3 = 0.f;
#pragma unroll
            for (int i = 0; i < 64; i += 4) {
                float4 h4 = *(const float4*)(hv + i);
                a0 = fmaf(w[i + 0], h4.x, a0);
                a1 = fmaf(w[i + 1], h4.y, a1);
                a2 = fmaf(w[i + 2], h4.z, a2);
                a3 = fmaf(w[i + 3], h4.w, a3);
            }
            zp[row * 9 + ck] = (a0 + a1) + (a2 + a3);
        }
        __syncthreads();   // zp ready (block-wide)

        // warp 0: gate-row sums + activations; 8 owners update state + publish
        if (tid < 32) {
            const float* zr = zp + tid * 9;
            float z = xg;
#pragma unroll
            for (int c = 0; c < 8; c++) z += zr[c];
            sact[tid] = ((tid >> 3) == 2) ? tanhap(z) : sigap(z);
        }
        __syncwarp();
        if (tid < 8) {
            float gi = sact[tid];
            float gf = sact[8 + tid];
            float gg = sact[16 + tid];
            float go_ = sact[24 + tid];
            c_state = gf * c_state + gi * gg;
            float h = go_ * tanhap(c_state);
            // publish FIRST: v = h + 4*(t%7), packed 2-per-b64, fire-and-forget
            float vv = h + coffp;
            float partner = __shfl_xor_sync(0x000000FFu, vv, 1);
            if ((tid & 1) == 0) {
                unsigned long long pk =
                    ((unsigned long long)__float_as_uint(partner) << 32) | __float_as_uint(vv);
                st_rlx64(&g_hx[dir][t & 1][j * 4 + (tid >> 1)], pk);
            }
            __stcg(hout + (size_t)pos * 1024 + (dir << 9) + hbase + tid, h);
        }
        kc = kp;
        kp = (kp == 6) ? 0 : kp + 1;
    }

    // exit/reset: make counters zero for the next launch / graph replay
    __syncthreads();
    if (tid == 0) {
        __threadfence();
        atomicAdd(&g_exit[dir][0], 1u);
        if (j == 0) {
            while (ld_acq(&g_exit[dir][0]) < (unsigned)RCTAS) { }
            g_cnt[dir][0] = 0u;
            __threadfence();
            atomicExch(&g_exit[dir][0], 0u);
        }
    }
}

// ---------------- pairwise MLP edge scores ----------------
__global__ void pair_score(const float* __restrict__ b1, const float* __restrict__ W2,
                           const float* __restrict__ b2) {
    __shared__ float Sh[32][101];
    __shared__ float Sm[32][101];
    __shared__ float sb1[MLPH], sw2[MLPH];
    int bh = blockIdx.y * 32, bm = blockIdx.x * 32;
    int tid = threadIdx.x;
    for (int i = tid; i < 32 * MLPH; i += 256) {
        int r = i / MLPH, c = i % MLPH;
        Sh[r][c] = g_sh[(size_t)(bh + r) * MLPH + c];
        Sm[r][c] = g_sm[(size_t)(bm + r) * MLPH + c];
    }
    if (tid < MLPH) { sb1[tid] = b1[tid]; sw2[tid] = W2[tid]; }
    __syncthreads();

    int tx = tid & 15, ty = tid >> 4;
    int h0 = ty * 2, m0 = tx * 2;
    float acc00 = 0.f, acc01 = 0.f, acc10 = 0.f, acc11 = 0.f;
    for (int jx = 0; jx < MLPH; jx++) {
        float w = sw2[jx], bb = sb1[jx];
        float a0 = Sh[h0][jx] + bb;
        float a1 = Sh[h0 + 1][jx] + bb;
        float c0 = Sm[m0][jx];
        float c1 = Sm[m0 + 1][jx];
        acc00 = fmaf(tanhap(a0 + c0), w, acc00);
        acc01 = fmaf(tanhap(a0 + c1), w, acc01);
        acc10 = fmaf(tanhap(a1 + c0), w, acc10);
        acc11 = fmaf(tanhap(a1 + c1), w, acc11);
    }
    float b2v = __ldg(b2);
    g_scores[(size_t)(bh + h0) * SEQ + bm + m0]         = acc00 + b2v;
    g_scores[(size_t)(bh + h0) * SEQ + bm + m0 + 1]     = acc01 + b2v;
    g_scores[(size_t)(bh + h0 + 1) * SEQ + bm + m0]     = acc10 + b2v;
    g_scores[(size_t)(bh + h0 + 1) * SEQ + bm + m0 + 1] = acc11 + b2v;
}

// ---------------- softmax over axis 0 ----------------
__global__ void softmax0(float* __restrict__ out) {
    int m = blockIdx.x;
    int tid = threadIdx.x;  // 128
    float v[4];
#pragma unroll
    for (int i = 0; i < 4; i++) v[i] = g_scores[(size_t)(tid + 128 * i) * SEQ + m];
    float mx = fmaxf(fmaxf(v[0], v[1]), fmaxf(v[2], v[3]));
    __shared__ float red[128];
    red[tid] = mx; __syncthreads();
    for (int o = 64; o > 0; o >>= 1) {
        if (tid < o) red[tid] = fmaxf(red[tid], red[tid + o]);
        __syncthreads();
    }
    mx = red[0]; __syncthreads();
    float e[4]; float ssum = 0.f;
#pragma unroll
    for (int i = 0; i < 4; i++) { e[i] = __expf(v[i] - mx); ssum += e[i]; }
    red[tid] = ssum; __syncthreads();
    for (int o = 64; o > 0; o >>= 1) {
        if (tid < o) red[tid] += red[tid + o];
        __syncthreads();
    }
    float inv = 1.f / red[0];
#pragma unroll
    for (int i = 0; i < 4; i++) out[(size_t)(tid + 128 * i) * SEQ + m] = e[i] * inv;
}

// ---------------- launch ----------------
extern "C" void kernel_launch(void* const* d_in, const int* in_sizes, int n_in,
                              void* d_out, int out_size) {
    const int*   wi  = (const int*)d_in[0];
    const int*   pi  = (const int*)d_in[1];
    const float* we  = (const float*)d_in[2];
    const float* pe  = (const float*)d_in[3];
    const float* wih0f = (const float*)d_in[4];
    const float* whh0f = (const float*)d_in[5];
    const float* b0f   = (const float*)d_in[6];
    const float* wih0b = (const float*)d_in[7];
    const float* whh0b = (const float*)d_in[8];
    const float* b0b   = (const float*)d_in[9];
    const float* wih1f = (const float*)d_in[10];
    const float* whh1f = (const float*)d_in[11];
    const float* b1f   = (const float*)d_in[12];
    const float* wih1b = (const float*)d_in[13];
    const float* whh1b = (const float*)d_in[14];
    const float* b1b   = (const float*)d_in[15];
    const float* W1    = (const float*)d_in[16];
    const float* b1    = (const float*)d_in[17];
    const float* W2    = (const float*)d_in[18];
    const float* b2    = (const float*)d_in[19];
    float* out = (float*)d_out;

    float *p_x0, *p_xw0, *p_xw1, *p_h0, *p_h1, *p_sh, *p_sm;
    cudaGetSymbolAddress((void**)&p_x0, g_x0);
    cudaGetSymbolAddress((void**)&p_xw0, g_xw0);
    cudaGetSymbolAddress((void**)&p_xw1, g_xw1);
    cudaGetSymbolAddress((void**)&p_h0, g_h0);
    cudaGetSymbolAddress((void**)&p_h1, g_h1);
    cudaGetSymbolAddress((void**)&p_sh, g_sh);
    cudaGetSymbolAddress((void**)&p_sm, g_sm);

    // 1. embeddings
    embed_kernel<<<SEQ, 256>>>(wi, pi, we, pe);

    // 2. layer0 input GEMMs (both directions in one launch, TF32 tensor cores)
    {
        dim3 grid(GATES / 64, SEQ / 128, 2);
        gemm_big<<<grid, 256>>>(p_x0, IN0, wih0f, wih0b, IN0, b0f, b0b,
                                p_xw0, p_xw1, GATES, SEQ, GATES, IN0);
    }

    // 3. layer0 recurrence
    lstm_layer<<<2 * RCTAS, 256>>>(whh0f, whh0b, p_xw0, p_xw1, p_h0);

    // 4. layer1 input GEMMs (both directions in one launch, TF32 tensor cores)
    {
        dim3 grid(GATES / 64, SEQ / 128, 2);
        gemm_big<<<grid, 256>>>(p_h0, IN1, wih1f, wih1b, IN1, b1f, b1b,
                                p_xw0, p_xw1, GATES, SEQ, GATES, IN1);
    }

    // 5. layer1 recurrence
    lstm_layer<<<2 * RCTAS, 256>>>(whh1f, whh1b, p_xw0, p_xw1, p_h1);

    // 6. MLP projections, both halves in one launch (W1 is [100, 2048] -> ldb = PAIRD)
    //    fp32 path (N=100; tensor tiles would starve it of CTAs)
    {
        dim3 grid((MLPH + 63) / 64, SEQ / 64, 2);
        gemm_dual<<<grid, 256>>>(p_h1, 2 * HID, W1, W1 + 1024, PAIRD, nullptr, nullptr,
                                 p_sh, p_sm, MLPH, SEQ, MLPH, 2 * HID);
    }

    // 7. pairwise scores
    {
        dim3 grid(SEQ / 32, SEQ / 32);
        pair_score<<<grid, 256>>>(b1, W2, b2);
    }

    // 8. softmax over heads (axis 0)
    softmax0<<<SEQ, 128>>>(out);
}

// round 15
// speedup vs baseline: 1.2896x; 1.0234x over previous
#include <cuda_runtime.h>
#include <math.h>
#include <stdint.h>

#define SEQ   512
#define HID   512
#define IN0   1088
#define IN1   1024
#define GATES 2048
#define MLPH  100
#define PAIRD 2048
#define RCTAS 64   // CTAs per LSTM direction
#define WIN   1.5f

// ---------------- device scratch (no allocations allowed) ----------------
__device__ float g_x0[SEQ * IN0];
__device__ float g_xw0[SEQ * GATES];
__device__ float g_xw1[SEQ * GATES];
__device__ float g_h0[SEQ * 2 * HID];
__device__ float g_h1[SEQ * 2 * HID];
__device__ float g_sh[SEQ * MLPH];
__device__ float g_sm[SEQ * MLPH];
__device__ float g_scores[SEQ * SEQ];
// self-validating h exchange: [dir][buffer=t&1][granule 0..255] (8B = 2 h values)
__device__ __align__(128) unsigned long long g_hx[2][2][256];
__device__ __align__(128) unsigned g_cnt[2][32];    // one-time start barrier
__device__ __align__(128) unsigned g_exit[2][32];   // exit/reset barrier

// ---------------- helpers ----------------
__device__ __forceinline__ unsigned ld_acq(const unsigned* p) {
    unsigned v;
    asm volatile("ld.acquire.gpu.u32 %0, [%1];" : "=r"(v) : "l"(p) : "memory");
    return v;
}
__device__ __forceinline__ unsigned long long ld_rlx64(const unsigned long long* p) {
    unsigned long long v;
    asm volatile("ld.relaxed.gpu.global.b64 %0, [%1];" : "=l"(v) : "l"(p) : "memory");
    return v;
}
__device__ __forceinline__ void st_rlx64(unsigned long long* p, unsigned long long v) {
    asm volatile("st.relaxed.gpu.global.b64 [%0], %1;" :: "l"(p), "l"(v) : "memory");
}
__device__ __forceinline__ float tanhap(float x) {             // HW tanh
    float y;
    asm("tanh.approx.f32 %0, %1;" : "=f"(y) : "f"(x));
    return y;
}
__device__ __forceinline__ float sigap(float x) {              // sigmoid via HW tanh
    return fmaf(0.5f, tanhap(0.5f * x), 0.5f);
}
__device__ __forceinline__ uint32_t tf32cvt(float x) {         // f32 -> tf32 bits
    uint32_t u;
    asm("cvt.rna.tf32.f32 %0, %1;" : "=r"(u) : "f"(x));
    return u;
}
__device__ __forceinline__ void mma_tf32(float* d, const uint32_t* a, const uint32_t* b) {
    asm volatile(
        "mma.sync.aligned.m16n8k8.row.col.f32.tf32.tf32.f32 "
        "{%0,%1,%2,%3}, {%4,%5,%6,%7}, {%8,%9}, {%0,%1,%2,%3};"
        : "+f"(d[0]), "+f"(d[1]), "+f"(d[2]), "+f"(d[3])
        : "r"(a[0]), "r"(a[1]), "r"(a[2]), "r"(a[3]), "r"(b[0]), "r"(b[1]));
}

// ---------------- embeddings ----------------
__global__ void embed_kernel(const int* __restrict__ wi, const int* __restrict__ pi,
                             const float* __restrict__ we, const float* __restrict__ pe) {
    int t = blockIdx.x;
    int w = wi[t], p = pi[t];
    const float* wr = we + (size_t)w * 1024;
    const float* pr = pe + (size_t)p * 64;
    float* out = g_x0 + (size_t)t * IN0;
    for (int i = threadIdx.x; i < 1024; i += blockDim.x) out[i] = wr[i];
    for (int i = threadIdx.x; i < 64; i += blockDim.x) out[1024 + i] = pr[i];
}

// ---- big dual GEMM on tensor cores: C[M,N] = A[M,K] * B[N,K]^T (+bias), TF32 mma ----
// BM=128, BN=64, BK=16, 256 threads = 8 warps. Smem holds PRE-CONVERTED tf32 bits.
// Strides 136/72 (== 8 mod 32): frag-load bank = 8*tig + gid + const -> 32 distinct
// banks, conflict-free (132/68 gave systematic 2-way conflicts -> L1 70%).
__global__ void __launch_bounds__(256, 2)
gemm_big(const float* __restrict__ A, int lda,
         const float* __restrict__ B0, const float* __restrict__ B1, int ldb,
         const float* __restrict__ bias0, const float* __restrict__ bias1,
         float* __restrict__ C0, float* __restrict__ C1, int ldc,
         int M, int N, int K) {
    const float* B = blockIdx.z ? B1 : B0;
    const float* bias = blockIdx.z ? bias1 : bias0;
    float* C = blockIdx.z ? C1 : C0;

    __shared__ __align__(16) uint32_t As[2][16][136];
    __shared__ __align__(16) uint32_t Bs[2][16][72];
    int bm = blockIdx.y * 128, bn = blockIdx.x * 64;
    int tid = threadIdx.x;
    int wid = tid >> 5, lane = tid & 31;
    int gid = lane >> 2, tig = lane & 3;
    int wm = (wid & 3) * 32;       // warp row offset in tile
    int wn = (wid >> 2) * 32;      // warp col offset in tile

    int lrA = tid >> 1;            // 0..127
    int lkA = (tid & 1) * 8;       // 0 or 8
    int lrB = tid >> 2;            // 0..63
    int lkB = (tid & 3) * 4;       // 0,4,8,12

    float acc[2][4][4];
#pragma unroll
    for (int mt = 0; mt < 2; mt++)
#pragma unroll
        for (int nt = 0; nt < 4; nt++)
#pragma unroll
            for (int r = 0; r < 4; r++) acc[mt][nt][r] = 0.f;

    int rowa = bm + lrA;
    int rowb = bn + lrB;
    bool a_ok = rowa < M;
    bool b_ok = rowb < N;

    // preload + store tile 0 into buffer 0
    float4 va0 = make_float4(0.f, 0.f, 0.f, 0.f), va1 = va0, vb = va0;
    if (a_ok) {
        const float* p = A + (size_t)rowa * lda;
        va0 = *(const float4*)(p + lkA); va1 = *(const float4*)(p + lkA + 4);
    }
    if (b_ok) vb = *(const float4*)(B + (size_t)rowb * ldb + lkB);
    As[0][lkA + 0][lrA] = tf32cvt(va0.x); As[0][lkA + 1][lrA] = tf32cvt(va0.y);
    As[0][lkA + 2][lrA] = tf32cvt(va0.z); As[0][lkA + 3][lrA] = tf32cvt(va0.w);
    As[0][lkA + 4][lrA] = tf32cvt(va1.x); As[0][lkA + 5][lrA] = tf32cvt(va1.y);
    As[0][lkA + 6][lrA] = tf32cvt(va1.z); As[0][lkA + 7][lrA] = tf32cvt(va1.w);
    Bs[0][lkB + 0][lrB] = tf32cvt(vb.x); Bs[0][lkB + 1][lrB] = tf32cvt(vb.y);
    Bs[0][lkB + 2][lrB] = tf32cvt(vb.z); Bs[0][lkB + 3][lrB] = tf32cvt(vb.w);
    __syncthreads();

    int cur = 0;
    for (int k0 = 0; k0 < K; k0 += 16) {
        bool has_next = (k0 + 16) < K;
        // issue global loads for the next tile (overlap with compute below)
        if (has_next) {
            if (a_ok) {
                const float* p = A + (size_t)rowa * lda + k0 + 16;
                va0 = *(const float4*)(p + lkA); va1 = *(const float4*)(p + lkA + 4);
            }
            if (b_ok) vb = *(const float4*)(B + (size_t)rowb * ldb + k0 + 16 + lkB);
        }
        // compute from buffer cur (frags are plain u32 loads, conflict-free)
#pragma unroll
        for (int ks = 0; ks < 2; ks++) {
            uint32_t afr[2][4];
#pragma unroll
            for (int mt = 0; mt < 2; mt++) {
                int r0 = wm + mt * 16 + gid;
                afr[mt][0] = As[cur][ks * 8 + tig][r0];
                afr[mt][1] = As[cur][ks * 8 + tig][r0 + 8];
                afr[mt][2] = As[cur][ks * 8 + 4 + tig][r0];
                afr[mt][3] = As[cur][ks * 8 + 4 + tig][r0 + 8];
            }
            uint32_t bfr[4][2];
#pragma unroll
            for (int nt = 0; nt < 4; nt++) {
                int c0 = wn + nt * 8 + gid;
                bfr[nt][0] = Bs[cur][ks * 8 + tig][c0];
                bfr[nt][1] = Bs[cur][ks * 8 + 4 + tig][c0];
            }
#pragma unroll
            for (int mt = 0; mt < 2; mt++)
#pragma unroll
                for (int nt = 0; nt < 4; nt++)
                    mma_tf32(acc[mt][nt], afr[mt], bfr[nt]);
        }
        // store next tile into the other buffer, single sync, swap
        if (has_next) {
            int nxt = cur ^ 1;
            As[nxt][lkA + 0][lrA] = tf32cvt(va0.x); As[nxt][lkA + 1][lrA] = tf32cvt(va0.y);
            As[nxt][lkA + 2][lrA] = tf32cvt(va0.z); As[nxt][lkA + 3][lrA] = tf32cvt(va0.w);
            As[nxt][lkA + 4][lrA] = tf32cvt(va1.x); As[nxt][lkA + 5][lrA] = tf32cvt(va1.y);
            As[nxt][lkA + 6][lrA] = tf32cvt(va1.z); As[nxt][lkA + 7][lrA] = tf32cvt(va1.w);
            Bs[nxt][lkB + 0][lrB] = tf32cvt(vb.x); Bs[nxt][lkB + 1][lrB] = tf32cvt(vb.y);
            Bs[nxt][lkB + 2][lrB] = tf32cvt(vb.z); Bs[nxt][lkB + 3][lrB] = tf32cvt(vb.w);
            __syncthreads();
            cur = nxt;
        }
    }

    // epilogue: c0 (gid, 2tig), c1 (gid, 2tig+1), c2 (gid+8, 2tig), c3 (gid+8, 2tig+1)
#pragma unroll
    for (int mt = 0; mt < 2; mt++) {
#pragma unroll
        for (int nt = 0; nt < 4; nt++) {
            int r = bm + wm + mt * 16 + gid;
            int c = bn + wn + nt * 8 + 2 * tig;
            float bv0 = bias ? bias[c] : 0.f;
            float bv1 = bias ? bias[c + 1] : 0.f;
            if (r < M && c < N) {
                C[(size_t)r * ldc + c]     = acc[mt][nt][0] + bv0;
                C[(size_t)r * ldc + c + 1] = acc[mt][nt][1] + bv1;
            }
            if (r + 8 < M && c < N) {
                C[(size_t)(r + 8) * ldc + c]     = acc[mt][nt][2] + bv0;
                C[(size_t)(r + 8) * ldc + c + 1] = acc[mt][nt][3] + bv1;
            }
        }
    }
}

// ---- dual GEMM: BM=64, BN=64, BK=16, 256 threads, 4x4 tile (fp32; N=100 MLP) ----
__global__ void gemm_dual(const float* __restrict__ A, int lda,
                          const float* __restrict__ B0, const float* __restrict__ B1, int ldb,
                          const float* __restrict__ bias0, const float* __restrict__ bias1,
                          float* __restrict__ C0, float* __restrict__ C1, int ldc,
                          int M, int N, int K) {
    const float* B = blockIdx.z ? B1 : B0;
    const float* bias = blockIdx.z ? bias1 : bias0;
    float* C = blockIdx.z ? C1 : C0;

    __shared__ __align__(16) float As[16][68];
    __shared__ __align__(16) float Bs[16][68];
    int bm = blockIdx.y * 64, bn = blockIdx.x * 64;
    int tid = threadIdx.x;
    int tx = tid & 15, ty = tid >> 4;
    int lr = tid >> 2;
    int lk = (tid & 3) * 4;

    float acc[4][4];
#pragma unroll
    for (int i = 0; i < 4; i++)
#pragma unroll
        for (int j = 0; j < 4; j++) acc[i][j] = 0.f;

    int rowa = bm + lr;
    int rowb = bn + lr;

    float4 va = make_float4(0.f, 0.f, 0.f, 0.f);
    float4 vb = make_float4(0.f, 0.f, 0.f, 0.f);
    if (rowa < M) va = *(const float4*)(A + (size_t)rowa * lda + lk);
    if (rowb < N) vb = *(const float4*)(B + (size_t)rowb * ldb + lk);

    for (int k0 = 0; k0 < K; k0 += 16) {
        As[lk + 0][lr] = va.x; As[lk + 1][lr] = va.y; As[lk + 2][lr] = va.z; As[lk + 3][lr] = va.w;
        Bs[lk + 0][lr] = vb.x; Bs[lk + 1][lr] = vb.y; Bs[lk + 2][lr] = vb.z; Bs[lk + 3][lr] = vb.w;
        __syncthreads();
        if (k0 + 16 < K) {
            va = make_float4(0.f, 0.f, 0.f, 0.f);
            vb = make_float4(0.f, 0.f, 0.f, 0.f);
            if (rowa < M) va = *(const float4*)(A + (size_t)rowa * lda + k0 + 16 + lk);
            if (rowb < N) vb = *(const float4*)(B + (size_t)rowb * ldb + k0 + 16 + lk);
        }
#pragma unroll
        for (int k = 0; k < 16; k++) {
            float4 a4 = *(const float4*)&As[k][ty * 4];
            float4 b4 = *(const float4*)&Bs[k][tx * 4];
            float a[4] = {a4.x, a4.y, a4.z, a4.w};
            float b[4] = {b4.x, b4.y, b4.z, b4.w};
#pragma unroll
            for (int i = 0; i < 4; i++)
#pragma unroll
                for (int j = 0; j < 4; j++) acc[i][j] = fmaf(a[i], b[j], acc[i][j]);
        }
        __syncthreads();
    }
#pragma unroll
    for (int i = 0; i < 4; i++) {
        int r = bm + ty * 4 + i;
        if (r >= M) continue;
#pragma unroll
        for (int j = 0; j < 4; j++) {
            int c = bn + tx * 4 + j;
            if (c < N) C[(size_t)r * ldc + c] = acc[i][j] + (bias ? bias[c] : 0.f);
        }
    }
}

// ---------------- LSTM recurrence: warp-private h slices + self-validating exchange -----
// (R11/R14-winning structure — protected, unchanged)
__global__ void __launch_bounds__(256, 1)
lstm_layer(const float* __restrict__ whh_f, const float* __restrict__ whh_b,
           const float* __restrict__ xw_f, const float* __restrict__ xw_b,
           float* __restrict__ hout) {
    __shared__ float sh[512];
    __shared__ float zp[32 * 9];
    __shared__ float sact[32];

    int dir = blockIdx.x >> 6;
    int j = blockIdx.x & 63;
    int hbase = j * 8;
    const float* W = dir ? whh_b : whh_f;
    const float* xw = dir ? xw_b : xw_f;
    int tid = threadIdx.x;
    int lane = tid & 31;

    int row = tid & 31;            // gate row within CTA (0..31)
    int ck = tid >> 5;             // K chunk == warp id (0..7)
    const int base = ck * 64;

    // weights into registers
    float w[64];
    {
        const float* src = W + (size_t)((row >> 3) * 512 + hbase + (row & 7)) * 512 + base;
#pragma unroll
        for (int i = 0; i < 64; i += 4) {
            float4 v = *(const float4*)(src + i);
            w[i] = v.x; w[i + 1] = v.y; w[i + 2] = v.z; w[i + 3] = v.w;
        }
    }

    // one-time: poison own hx granules, then grid start-barrier (per direction)
    if (tid == 0) {
        unsigned long long poison =
            ((unsigned long long)__float_as_uint(1e30f) << 32) | __float_as_uint(1e30f);
#pragma unroll
        for (int b = 0; b < 2; b++)
#pragma unroll
            for (int q = 0; q < 4; q++)
                st_rlx64(&g_hx[dir][b][j * 4 + q], poison);
        __threadfence();
        atomicAdd(&g_cnt[dir][0], 1u);
        while (ld_acq(&g_cnt[dir][0]) < (unsigned)RCTAS) { }
    }
    __syncthreads();

    float c_state = 0.f;           // owned by threads 0..7
    int kp = 0, kc = 0;            // t mod 7 (producer), (t-1) mod 7 (consumer)
    const int gran = ck * 32 + lane;   // this lane's granule (warp-private slice)

    for (int t = 0; t < 512; t++) {
        int pos = dir ? (511 - t) : t;
        float coffp = 4.0f * (float)kp;
        float coffc = 4.0f * (float)kc;

        // prefetch gate inputs (independent of h) — overlaps the poll below
        float xg = 0.f;
        if (tid < 32) {
            const float* xr = xw + (size_t)pos * GATES + (tid >> 3) * 512 + hbase + (tid & 7);
            xg = __ldg(xr);
        }

        // per-warp gather: lane polls its warp's granule; sh slice is warp-private
        if (t == 0) {
            ((float2*)sh)[gran] = make_float2(0.f, 0.f);
        } else {
            const unsigned long long* src = &g_hx[dir][(t - 1) & 1][gran];
            float lo, hi;
            for (;;) {
                unsigned long long v = ld_rlx64(src);
                lo = __uint_as_float((unsigned)v);
                hi = __uint_as_float((unsigned)(v >> 32));
                if (fabsf(lo - coffc) <= WIN && fabsf(hi - coffc) <= WIN) break;
            }
            ((float2*)sh)[gran] = make_float2(lo - coffc, hi - coffc);
        }
        __syncwarp();      // warp-local: this warp's sh slice ready

        // matvec partial: register weights x warp-private smem h slice
        {
            const float* hv = sh + base;
            float a0 = 0.f, a1 = 0.f, a2 = 0.f, a3 = 0.f;
#pragma unroll
            for (int i = 0; i < 64; i += 4) {
                float4 h4 = *(const float4*)(hv + i);
                a0 = fmaf(w[i + 0], h4.x, a0);
                a1 = fmaf(w[i + 1], h4.y, a1);
                a2 = fmaf(w[i + 2], h4.z, a2);
                a3 = fmaf(w[i + 3], h4.w, a3);
            }
            zp[row * 9 + ck] = (a0 + a1) + (a2 + a3);
        }
        __syncthreads();   // zp ready (block-wide)

        // warp 0: gate-row sums + activations; 8 owners update state + publish
        if (tid < 32) {
            const float* zr = zp + tid * 9;
            float z = xg;
#pragma unroll
            for (int c = 0; c < 8; c++) z += zr[c];
            sact[tid] = ((tid >> 3) == 2) ? tanhap(z) : sigap(z);
        }
        __syncwarp();
        if (tid < 8) {
            float gi = sact[tid];
            float gf = sact[8 + tid];
            float gg = sact[16 + tid];
            float go_ = sact[24 + tid];
            c_state = gf * c_state + gi * gg;
            float h = go_ * tanhap(c_state);
            // publish FIRST: v = h + 4*(t%7), packed 2-per-b64, fire-and-forget
            float vv = h + coffp;
            float partner = __shfl_xor_sync(0x000000FFu, vv, 1);
            if ((tid & 1) == 0) {
                unsigned long long pk =
                    ((unsigned long long)__float_as_uint(partner) << 32) | __float_as_uint(vv);
                st_rlx64(&g_hx[dir][t & 1][j * 4 + (tid >> 1)], pk);
            }
            __stcg(hout + (size_t)pos * 1024 + (dir << 9) + hbase + tid, h);
        }
        kc = kp;
        kp = (kp == 6) ? 0 : kp + 1;
    }

    // exit/reset: make counters zero for the next launch / graph replay
    __syncthreads();
    if (tid == 0) {
        __threadfence();
        atomicAdd(&g_exit[dir][0], 1u);
        if (j == 0) {
            while (ld_acq(&g_exit[dir][0]) < (unsigned)RCTAS) { }
            g_cnt[dir][0] = 0u;
            __threadfence();
            atomicExch(&g_exit[dir][0], 0u);
        }
    }
}

// ---------------- pairwise MLP edge scores ----------------
__global__ void pair_score(const float* __restrict__ b1, const float* __restrict__ W2,
                           const float* __restrict__ b2) {
    __shared__ float Sh[32][101];
    __shared__ float Sm[32][101];
    __shared__ float sb1[MLPH], sw2[MLPH];
    int bh = blockIdx.y * 32, bm = blockIdx.x * 32;
    int tid = threadIdx.x;
    for (int i = tid; i < 32 * MLPH; i += 256) {
        int r = i / MLPH, c = i % MLPH;
        Sh[r][c] = g_sh[(size_t)(bh + r) * MLPH + c];
        Sm[r][c] = g_sm[(size_t)(bm + r) * MLPH + c];
    }
    if (tid < MLPH) { sb1[tid] = b1[tid]; sw2[tid] = W2[tid]; }
    __syncthreads();

    int tx = tid & 15, ty = tid >> 4;
    int h0 = ty * 2, m0 = tx * 2;
    float acc00 = 0.f, acc01 = 0.f, acc10 = 0.f, acc11 = 0.f;
    for (int jx = 0; jx < MLPH; jx++) {
        float w = sw2[jx], bb = sb1[jx];
        float a0 = Sh[h0][jx] + bb;
        float a1 = Sh[h0 + 1][jx] + bb;
        float c0 = Sm[m0][jx];
        float c1 = Sm[m0 + 1][jx];
        acc00 = fmaf(tanhap(a0 + c0), w, acc00);
        acc01 = fmaf(tanhap(a0 + c1), w, acc01);
        acc10 = fmaf(tanhap(a1 + c0), w, acc10);
        acc11 = fmaf(tanhap(a1 + c1), w, acc11);
    }
    float b2v = __ldg(b2);
    g_scores[(size_t)(bh + h0) * SEQ + bm + m0]         = acc00 + b2v;
    g_scores[(size_t)(bh + h0) * SEQ + bm + m0 + 1]     = acc01 + b2v;
    g_scores[(size_t)(bh + h0 + 1) * SEQ + bm + m0]     = acc10 + b2v;
    g_scores[(size_t)(bh + h0 + 1) * SEQ + bm + m0 + 1] = acc11 + b2v;
}

// ---------------- softmax over axis 0 ----------------
__global__ void softmax0(float* __restrict__ out) {
    int m = blockIdx.x;
    int tid = threadIdx.x;  // 128
    float v[4];
#pragma unroll
    for (int i = 0; i < 4; i++) v[i] = g_scores[(size_t)(tid + 128 * i) * SEQ + m];
    float mx = fmaxf(fmaxf(v[0], v[1]), fmaxf(v[2], v[3]));
    __shared__ float red[128];
    red[tid] = mx; __syncthreads();
    for (int o = 64; o > 0; o >>= 1) {
        if (tid < o) red[tid] = fmaxf(red[tid], red[tid + o]);
        __syncthreads();
    }
    mx = red[0]; __syncthreads();
    float e[4]; float ssum = 0.f;
#pragma unroll
    for (int i = 0; i < 4; i++) { e[i] = __expf(v[i] - mx); ssum += e[i]; }
    red[tid] = ssum; __syncthreads();
    for (int o = 64; o > 0; o >>= 1) {
        if (tid < o) red[tid] += red[tid + o];
        __syncthreads();
    }
    float inv = 1.f / red[0];
#pragma unroll
    for (int i = 0; i < 4; i++) out[(size_t)(tid + 128 * i) * SEQ + m] = e[i] * inv;
}

// ---------------- launch ----------------
extern "C" void kernel_launch(void* const* d_in, const int* in_sizes, int n_in,
                              void* d_out, int out_size) {
    const int*   wi  = (const int*)d_in[0];
    const int*   pi  = (const int*)d_in[1];
    const float* we  = (const float*)d_in[2];
    const float* pe  = (const float*)d_in[3];
    const float* wih0f = (const float*)d_in[4];
    const float* whh0f = (const float*)d_in[5];
    const float* b0f   = (const float*)d_in[6];
    const float* wih0b = (const float*)d_in[7];
    const float* whh0b = (const float*)d_in[8];
    const float* b0b   = (const float*)d_in[9];
    const float* wih1f = (const float*)d_in[10];
    const float* whh1f = (const float*)d_in[11];
    const float* b1f   = (const float*)d_in[12];
    const float* wih1b = (const float*)d_in[13];
    const float* whh1b = (const float*)d_in[14];
    const float* b1b   = (const float*)d_in[15];
    const float* W1    = (const float*)d_in[16];
    const float* b1    = (const float*)d_in[17];
    const float* W2    = (const float*)d_in[18];
    const float* b2    = (const float*)d_in[19];
    float* out = (float*)d_out;

    float *p_x0, *p_xw0, *p_xw1, *p_h0, *p_h1, *p_sh, *p_sm;
    cudaGetSymbolAddress((void**)&p_x0, g_x0);
    cudaGetSymbolAddress((void**)&p_xw0, g_xw0);
    cudaGetSymbolAddress((void**)&p_xw1, g_xw1);
    cudaGetSymbolAddress((void**)&p_h0, g_h0);
    cudaGetSymbolAddress((void**)&p_h1, g_h1);
    cudaGetSymbolAddress((void**)&p_sh, g_sh);
    cudaGetSymbolAddress((void**)&p_sm, g_sm);

    // 1. embeddings
    embed_kernel<<<SEQ, 256>>>(wi, pi, we, pe);

    // 2. layer0 input GEMMs (both directions in one launch, TF32 tensor cores)
    {
        dim3 grid(GATES / 64, SEQ / 128, 2);
        gemm_big<<<grid, 256>>>(p_x0, IN0, wih0f, wih0b, IN0, b0f, b0b,
                                p_xw0, p_xw1, GATES, SEQ, GATES, IN0);
    }

    // 3. layer0 recurrence
    lstm_layer<<<2 * RCTAS, 256>>>(whh0f, whh0b, p_xw0, p_xw1, p_h0);

    // 4. layer1 input GEMMs (both directions in one launch, TF32 tensor cores)
    {
        dim3 grid(GATES / 64, SEQ / 128, 2);
        gemm_big<<<grid, 256>>>(p_h0, IN1, wih1f, wih1b, IN1, b1f, b1b,
                                p_xw0, p_xw1, GATES, SEQ, GATES, IN1);
    }

    // 5. layer1 recurrence
    lstm_layer<<<2 * RCTAS, 256>>>(whh1f, whh1b, p_xw0, p_xw1, p_h1);

    // 6. MLP projections, both halves in one launch (W1 is [100, 2048] -> ldb = PAIRD)
    //    fp32 path (N=100; tensor tiles would starve it of CTAs)
    {
        dim3 grid((MLPH + 63) / 64, SEQ / 64, 2);
        gemm_dual<<<grid, 256>>>(p_h1, 2 * HID, W1, W1 + 1024, PAIRD, nullptr, nullptr,
                                 p_sh, p_sm, MLPH, SEQ, MLPH, 2 * HID);
    }

    // 7. pairwise scores
    {
        dim3 grid(SEQ / 32, SEQ / 32);
        pair_score<<<grid, 256>>>(b1, W2, b2);
    }

    // 8. softmax over heads (axis 0)
    softmax0<<<SEQ, 128>>>(out);
}

// round 16
// speedup vs baseline: 1.2942x; 1.0035x over previous
#include <cuda_runtime.h>
#include <math.h>
#include <stdint.h>

#define SEQ   512
#define HID   512
#define IN0   1088
#define IN1   1024
#define GATES 2048
#define MLPH  100
#define PAIRD 2048
#define RCTAS 64   // CTAs per LSTM direction
#define WIN   1.5f

// ---------------- device scratch (no allocations allowed) ----------------
__device__ float g_x0[SEQ * IN0];
__device__ float g_xw0[SEQ * GATES];
__device__ float g_xw1[SEQ * GATES];
__device__ float g_h0[SEQ * 2 * HID];
__device__ float g_h1[SEQ * 2 * HID];
__device__ float g_sh[SEQ * MLPH];
__device__ float g_sm[SEQ * MLPH];
__device__ float g_scores[SEQ * SEQ];
// self-validating h exchange: [dir][buffer=t&1][granule 0..255] (8B = 2 h values)
__device__ __align__(128) unsigned long long g_hx[2][2][256];
__device__ __align__(128) unsigned g_cnt[2][32];    // one-time start barrier
__device__ __align__(128) unsigned g_exit[2][32];   // exit/reset barrier

// ---------------- helpers ----------------
__device__ __forceinline__ unsigned ld_acq(const unsigned* p) {
    unsigned v;
    asm volatile("ld.acquire.gpu.u32 %0, [%1];" : "=r"(v) : "l"(p) : "memory");
    return v;
}
__device__ __forceinline__ unsigned long long ld_rlx64(const unsigned long long* p) {
    unsigned long long v;
    asm volatile("ld.relaxed.gpu.global.b64 %0, [%1];" : "=l"(v) : "l"(p) : "memory");
    return v;
}
__device__ __forceinline__ void st_rlx64(unsigned long long* p, unsigned long long v) {
    asm volatile("st.relaxed.gpu.global.b64 [%0], %1;" :: "l"(p), "l"(v) : "memory");
}
__device__ __forceinline__ float tanhap(float x) {             // HW tanh
    float y;
    asm("tanh.approx.f32 %0, %1;" : "=f"(y) : "f"(x));
    return y;
}
__device__ __forceinline__ float sigap(float x) {              // sigmoid via HW tanh
    return fmaf(0.5f, tanhap(0.5f * x), 0.5f);
}
__device__ __forceinline__ uint32_t tf32cvt(float x) {         // f32 -> tf32 bits
    uint32_t u;
    asm("cvt.rna.tf32.f32 %0, %1;" : "=r"(u) : "f"(x));
    return u;
}
__device__ __forceinline__ void mma_tf32(float* d, const uint32_t* a, const uint32_t* b) {
    asm volatile(
        "mma.sync.aligned.m16n8k8.row.col.f32.tf32.tf32.f32 "
        "{%0,%1,%2,%3}, {%4,%5,%6,%7}, {%8,%9}, {%0,%1,%2,%3};"
        : "+f"(d[0]), "+f"(d[1]), "+f"(d[2]), "+f"(d[3])
        : "r"(a[0]), "r"(a[1]), "r"(a[2]), "r"(a[3]), "r"(b[0]), "r"(b[1]));
}
// packed fp32x2 (Blackwell): 2 IEEE fp32 FMAs per instruction
__device__ __forceinline__ unsigned long long pack2(float lo, float hi) {
    unsigned long long r;
    asm("mov.b64 %0, {%1, %2};" : "=l"(r) : "f"(lo), "f"(hi));
    return r;
}
__device__ __forceinline__ unsigned long long fma2(unsigned long long a,
                                                   unsigned long long b,
                                                   unsigned long long c) {
    unsigned long long d;
    asm("fma.rn.f32x2 %0, %1, %2, %3;" : "=l"(d) : "l"(a), "l"(b), "l"(c));
    return d;
}
__device__ __forceinline__ void unpack2(float& lo, float& hi, unsigned long long v) {
    asm("mov.b64 {%0, %1}, %2;" : "=f"(lo), "=f"(hi) : "l"(v));
}

// ---------------- embeddings ----------------
__global__ void embed_kernel(const int* __restrict__ wi, const int* __restrict__ pi,
                             const float* __restrict__ we, const float* __restrict__ pe) {
    int t = blockIdx.x;
    int w = wi[t], p = pi[t];
    const float* wr = we + (size_t)w * 1024;
    const float* pr = pe + (size_t)p * 64;
    float* out = g_x0 + (size_t)t * IN0;
    for (int i = threadIdx.x; i < 1024; i += blockDim.x) out[i] = wr[i];
    for (int i = threadIdx.x; i < 64; i += blockDim.x) out[1024 + i] = pr[i];
}

// ---- big dual GEMM on tensor cores: C[M,N] = A[M,K] * B[N,K]^T (+bias), TF32 mma ----
// BM=128, BN=64, BK=16, 256 threads = 8 warps. Smem holds PRE-CONVERTED tf32 bits.
// Strides 136/72 (== 8 mod 32): frag-load banks conflict-free.
__global__ void __launch_bounds__(256, 2)
gemm_big(const float* __restrict__ A, int lda,
         const float* __restrict__ B0, const float* __restrict__ B1, int ldb,
         const float* __restrict__ bias0, const float* __restrict__ bias1,
         float* __restrict__ C0, float* __restrict__ C1, int ldc,
         int M, int N, int K) {
    const float* B = blockIdx.z ? B1 : B0;
    const float* bias = blockIdx.z ? bias1 : bias0;
    float* C = blockIdx.z ? C1 : C0;

    __shared__ __align__(16) uint32_t As[2][16][136];
    __shared__ __align__(16) uint32_t Bs[2][16][72];
    int bm = blockIdx.y * 128, bn = blockIdx.x * 64;
    int tid = threadIdx.x;
    int wid = tid >> 5, lane = tid & 31;
    int gid = lane >> 2, tig = lane & 3;
    int wm = (wid & 3) * 32;
    int wn = (wid >> 2) * 32;

    int lrA = tid >> 1;
    int lkA = (tid & 1) * 8;
    int lrB = tid >> 2;
    int lkB = (tid & 3) * 4;

    float acc[2][4][4];
#pragma unroll
    for (int mt = 0; mt < 2; mt++)
#pragma unroll
        for (int nt = 0; nt < 4; nt++)
#pragma unroll
            for (int r = 0; r < 4; r++) acc[mt][nt][r] = 0.f;

    int rowa = bm + lrA;
    int rowb = bn + lrB;
    bool a_ok = rowa < M;
    bool b_ok = rowb < N;

    float4 va0 = make_float4(0.f, 0.f, 0.f, 0.f), va1 = va0, vb = va0;
    if (a_ok) {
        const float* p = A + (size_t)rowa * lda;
        va0 = *(const float4*)(p + lkA); va1 = *(const float4*)(p + lkA + 4);
    }
    if (b_ok) vb = *(const float4*)(B + (size_t)rowb * ldb + lkB);
    As[0][lkA + 0][lrA] = tf32cvt(va0.x); As[0][lkA + 1][lrA] = tf32cvt(va0.y);
    As[0][lkA + 2][lrA] = tf32cvt(va0.z); As[0][lkA + 3][lrA] = tf32cvt(va0.w);
    As[0][lkA + 4][lrA] = tf32cvt(va1.x); As[0][lkA + 5][lrA] = tf32cvt(va1.y);
    As[0][lkA + 6][lrA] = tf32cvt(va1.z); As[0][lkA + 7][lrA] = tf32cvt(va1.w);
    Bs[0][lkB + 0][lrB] = tf32cvt(vb.x); Bs[0][lkB + 1][lrB] = tf32cvt(vb.y);
    Bs[0][lkB + 2][lrB] = tf32cvt(vb.z); Bs[0][lkB + 3][lrB] = tf32cvt(vb.w);
    __syncthreads();

    int cur = 0;
    for (int k0 = 0; k0 < K; k0 += 16) {
        bool has_next = (k0 + 16) < K;
        if (has_next) {
            if (a_ok) {
                const float* p = A + (size_t)rowa * lda + k0 + 16;
                va0 = *(const float4*)(p + lkA); va1 = *(const float4*)(p + lkA + 4);
            }
            if (b_ok) vb = *(const float4*)(B + (size_t)rowb * ldb + k0 + 16 + lkB);
        }
#pragma unroll
        for (int ks = 0; ks < 2; ks++) {
            uint32_t afr[2][4];
#pragma unroll
            for (int mt = 0; mt < 2; mt++) {
                int r0 = wm + mt * 16 + gid;
                afr[mt][0] = As[cur][ks * 8 + tig][r0];
                afr[mt][1] = As[cur][ks * 8 + tig][r0 + 8];
                afr[mt][2] = As[cur][ks * 8 + 4 + tig][r0];
                afr[mt][3] = As[cur][ks * 8 + 4 + tig][r0 + 8];
            }
            uint32_t bfr[4][2];
#pragma unroll
            for (int nt = 0; nt < 4; nt++) {
                int c0 = wn + nt * 8 + gid;
                bfr[nt][0] = Bs[cur][ks * 8 + tig][c0];
                bfr[nt][1] = Bs[cur][ks * 8 + 4 + tig][c0];
            }
#pragma unroll
            for (int mt = 0; mt < 2; mt++)
#pragma unroll
                for (int nt = 0; nt < 4; nt++)
                    mma_tf32(acc[mt][nt], afr[mt], bfr[nt]);
        }
        if (has_next) {
            int nxt = cur ^ 1;
            As[nxt][lkA + 0][lrA] = tf32cvt(va0.x); As[nxt][lkA + 1][lrA] = tf32cvt(va0.y);
            As[nxt][lkA + 2][lrA] = tf32cvt(va0.z); As[nxt][lkA + 3][lrA] = tf32cvt(va0.w);
            As[nxt][lkA + 4][lrA] = tf32cvt(va1.x); As[nxt][lkA + 5][lrA] = tf32cvt(va1.y);
            As[nxt][lkA + 6][lrA] = tf32cvt(va1.z); As[nxt][lkA + 7][lrA] = tf32cvt(va1.w);
            Bs[nxt][lkB + 0][lrB] = tf32cvt(vb.x); Bs[nxt][lkB + 1][lrB] = tf32cvt(vb.y);
            Bs[nxt][lkB + 2][lrB] = tf32cvt(vb.z); Bs[nxt][lkB + 3][lrB] = tf32cvt(vb.w);
            __syncthreads();
            cur = nxt;
        }
    }

#pragma unroll
    for (int mt = 0; mt < 2; mt++) {
#pragma unroll
        for (int nt = 0; nt < 4; nt++) {
            int r = bm + wm + mt * 16 + gid;
            int c = bn + wn + nt * 8 + 2 * tig;
            float bv0 = bias ? bias[c] : 0.f;
            float bv1 = bias ? bias[c + 1] : 0.f;
            if (r < M && c < N) {
                C[(size_t)r * ldc + c]     = acc[mt][nt][0] + bv0;
                C[(size_t)r * ldc + c + 1] = acc[mt][nt][1] + bv1;
            }
            if (r + 8 < M && c < N) {
                C[(size_t)(r + 8) * ldc + c]     = acc[mt][nt][2] + bv0;
                C[(size_t)(r + 8) * ldc + c + 1] = acc[mt][nt][3] + bv1;
            }
        }
    }
}

// ---- dual GEMM: BM=64, BN=64, BK=16, 256 threads, 4x4 tile (fp32; N=100 MLP) ----
__global__ void gemm_dual(const float* __restrict__ A, int lda,
                          const float* __restrict__ B0, const float* __restrict__ B1, int ldb,
                          const float* __restrict__ bias0, const float* __restrict__ bias1,
                          float* __restrict__ C0, float* __restrict__ C1, int ldc,
                          int M, int N, int K) {
    const float* B = blockIdx.z ? B1 : B0;
    const float* bias = blockIdx.z ? bias1 : bias0;
    float* C = blockIdx.z ? C1 : C0;

    __shared__ __align__(16) float As[16][68];
    __shared__ __align__(16) float Bs[16][68];
    int bm = blockIdx.y * 64, bn = blockIdx.x * 64;
    int tid = threadIdx.x;
    int tx = tid & 15, ty = tid >> 4;
    int lr = tid >> 2;
    int lk = (tid & 3) * 4;

    float acc[4][4];
#pragma unroll
    for (int i = 0; i < 4; i++)
#pragma unroll
        for (int j = 0; j < 4; j++) acc[i][j] = 0.f;

    int rowa = bm + lr;
    int rowb = bn + lr;

    float4 va = make_float4(0.f, 0.f, 0.f, 0.f);
    float4 vb = make_float4(0.f, 0.f, 0.f, 0.f);
    if (rowa < M) va = *(const float4*)(A + (size_t)rowa * lda + lk);
    if (rowb < N) vb = *(const float4*)(B + (size_t)rowb * ldb + lk);

    for (int k0 = 0; k0 < K; k0 += 16) {
        As[lk + 0][lr] = va.x; As[lk + 1][lr] = va.y; As[lk + 2][lr] = va.z; As[lk + 3][lr] = va.w;
        Bs[lk + 0][lr] = vb.x; Bs[lk + 1][lr] = vb.y; Bs[lk + 2][lr] = vb.z; Bs[lk + 3][lr] = vb.w;
        __syncthreads();
        if (k0 + 16 < K) {
            va = make_float4(0.f, 0.f, 0.f, 0.f);
            vb = make_float4(0.f, 0.f, 0.f, 0.f);
            if (rowa < M) va = *(const float4*)(A + (size_t)rowa * lda + k0 + 16 + lk);
            if (rowb < N) vb = *(const float4*)(B + (size_t)rowb * ldb + k0 + 16 + lk);
        }
#pragma unroll
        for (int k = 0; k < 16; k++) {
            float4 a4 = *(const float4*)&As[k][ty * 4];
            float4 b4 = *(const float4*)&Bs[k][tx * 4];
            float a[4] = {a4.x, a4.y, a4.z, a4.w};
            float b[4] = {b4.x, b4.y, b4.z, b4.w};
#pragma unroll
            for (int i = 0; i < 4; i++)
#pragma unroll
                for (int j = 0; j < 4; j++) acc[i][j] = fmaf(a[i], b[j], acc[i][j]);
        }
        __syncthreads();
    }
#pragma unroll
    for (int i = 0; i < 4; i++) {
        int r = bm + ty * 4 + i;
        if (r >= M) continue;
#pragma unroll
        for (int j = 0; j < 4; j++) {
            int c = bn + tx * 4 + j;
            if (c < N) C[(size_t)r * ldc + c] = acc[i][j] + (bias ? bias[c] : 0.f);
        }
    }
}

// ---------------- LSTM recurrence: warp-private h slices + self-validating exchange -----
// (R11/R14 protocol protected; matvec arithmetic converted to packed fma.rn.f32x2:
//  2 IEEE fp32 FMAs per instruction -> FMA issue halved, same smem LDS.128 count)
__global__ void __launch_bounds__(256, 1)
lstm_layer(const float* __restrict__ whh_f, const float* __restrict__ whh_b,
           const float* __restrict__ xw_f, const float* __restrict__ xw_b,
           float* __restrict__ hout) {
    __shared__ __align__(16) float sh[512];
    __shared__ float zp[32 * 9];
    __shared__ float sact[32];

    int dir = blockIdx.x >> 6;
    int j = blockIdx.x & 63;
    int hbase = j * 8;
    const float* W = dir ? whh_b : whh_f;
    const float* xw = dir ? xw_b : xw_f;
    int tid = threadIdx.x;
    int lane = tid & 31;

    int row = tid & 31;            // gate row within CTA (0..31)
    int ck = tid >> 5;             // K chunk == warp id (0..7)
    const int base = ck * 64;

    // weights into registers, packed as 32 fp32x2 pairs
    unsigned long long wp[32];
    {
        const float* src = W + (size_t)((row >> 3) * 512 + hbase + (row & 7)) * 512 + base;
#pragma unroll
        for (int i = 0; i < 64; i += 4) {
            float4 v = *(const float4*)(src + i);
            wp[i / 2]     = pack2(v.x, v.y);
            wp[i / 2 + 1] = pack2(v.z, v.w);
        }
    }

    // one-time: poison own hx granules, then grid start-barrier (per direction)
    if (tid == 0) {
        unsigned long long poison =
            ((unsigned long long)__float_as_uint(1e30f) << 32) | __float_as_uint(1e30f);
#pragma unroll
        for (int b = 0; b < 2; b++)
#pragma unroll
            for (int q = 0; q < 4; q++)
                st_rlx64(&g_hx[dir][b][j * 4 + q], poison);
        __threadfence();
        atomicAdd(&g_cnt[dir][0], 1u);
        while (ld_acq(&g_cnt[dir][0]) < (unsigned)RCTAS) { }
    }
    __syncthreads();

    float c_state = 0.f;           // owned by threads 0..7
    int kp = 0, kc = 0;            // t mod 7 (producer), (t-1) mod 7 (consumer)
    const int gran = ck * 32 + lane;   // this lane's granule (warp-private slice)

    for (int t = 0; t < 512; t++) {
        int pos = dir ? (511 - t) : t;
        float coffp = 4.0f * (float)kp;
        float coffc = 4.0f * (float)kc;

        // prefetch gate inputs (independent of h) — overlaps the poll below
        float xg = 0.f;
        if (tid < 32) {
            const float* xr = xw + (size_t)pos * GATES + (tid >> 3) * 512 + hbase + (tid & 7);
            xg = __ldg(xr);
        }

        // per-warp gather: lane polls its warp's granule; sh slice is warp-private
        if (t == 0) {
            ((float2*)sh)[gran] = make_float2(0.f, 0.f);
        } else {
            const unsigned long long* src = &g_hx[dir][(t - 1) & 1][gran];
            float lo, hi;
            for (;;) {
                unsigned long long v = ld_rlx64(src);
                lo = __uint_as_float((unsigned)v);
                hi = __uint_as_float((unsigned)(v >> 32));
                if (fabsf(lo - coffc) <= WIN && fabsf(hi - coffc) <= WIN) break;
            }
            ((float2*)sh)[gran] = make_float2(lo - coffc, hi - coffc);
        }
        __syncwarp();      // warp-local: this warp's sh slice ready

        // matvec partial: packed f32x2 FMAs, 16 LDS.128 feeding 32 dual-FMA
        {
            const ulonglong2* hp2 = (const ulonglong2*)(sh + base);
            unsigned long long A0 = 0ull, A1 = 0ull, A2 = 0ull, A3 = 0ull;
#pragma unroll
            for (int i = 0; i < 16; i += 2) {
                ulonglong2 ha = hp2[i];
                ulonglong2 hb = hp2[i + 1];
                A0 = fma2(wp[2 * i],     ha.x, A0);
                A1 = fma2(wp[2 * i + 1], ha.y, A1);
                A2 = fma2(wp[2 * i + 2], hb.x, A2);
                A3 = fma2(wp[2 * i + 3], hb.y, A3);
            }
            float s0, s1, s2, s3, s4, s5, s6, s7;
            unpack2(s0, s1, A0);
            unpack2(s2, s3, A1);
            unpack2(s4, s5, A2);
            unpack2(s6, s7, A3);
            zp[row * 9 + ck] = ((s0 + s1) + (s2 + s3)) + ((s4 + s5) + (s6 + s7));
        }
        __syncthreads();   // zp ready (block-wide)

        // warp 0: gate-row sums + activations; 8 owners update state + publish
        if (tid < 32) {
            const float* zr = zp + tid * 9;
            float z = xg;
#pragma unroll
            for (int c = 0; c < 8; c++) z += zr[c];
            sact[tid] = ((tid >> 3) == 2) ? tanhap(z) : sigap(z);
        }
        __syncwarp();
        if (tid < 8) {
            float gi = sact[tid];
            float gf = sact[8 + tid];
            float gg = sact[16 + tid];
            float go_ = sact[24 + tid];
            c_state = gf * c_state + gi * gg;
            float h = go_ * tanhap(c_state);
            // publish FIRST: v = h + 4*(t%7), packed 2-per-b64, fire-and-forget
            float vv = h + coffp;
            float partner = __shfl_xor_sync(0x000000FFu, vv, 1);
            if ((tid & 1) == 0) {
                unsigned long long pk =
                    ((unsigned long long)__float_as_uint(partner) << 32) | __float_as_uint(vv);
                st_rlx64(&g_hx[dir][t & 1][j * 4 + (tid >> 1)], pk);
            }
            __stcg(hout + (size_t)pos * 1024 + (dir << 9) + hbase + tid, h);
        }
        kc = kp;
        kp = (kp == 6) ? 0 : kp + 1;
    }

    // exit/reset: make counters zero for the next launch / graph replay
    __syncthreads();
    if (tid == 0) {
        __threadfence();
        atomicAdd(&g_exit[dir][0], 1u);
        if (j == 0) {
            while (ld_acq(&g_exit[dir][0]) < (unsigned)RCTAS) { }
            g_cnt[dir][0] = 0u;
            __threadfence();
            atomicExch(&g_exit[dir][0], 0u);
        }
    }
}

// ---------------- pairwise MLP edge scores ----------------
__global__ void pair_score(const float* __restrict__ b1, const float* __restrict__ W2,
                           const float* __restrict__ b2) {
    __shared__ float Sh[32][101];
    __shared__ float Sm[32][101];
    __shared__ float sb1[MLPH], sw2[MLPH];
    int bh = blockIdx.y * 32, bm = blockIdx.x * 32;
    int tid = threadIdx.x;
    for (int i = tid; i < 32 * MLPH; i += 256) {
        int r = i / MLPH, c = i % MLPH;
        Sh[r][c] = g_sh[(size_t)(bh + r) * MLPH + c];
        Sm[r][c] = g_sm[(size_t)(bm + r) * MLPH + c];
    }
    if (tid < MLPH) { sb1[tid] = b1[tid]; sw2[tid] = W2[tid]; }
    __syncthreads();

    int tx = tid & 15, ty = tid >> 4;
    int h0 = ty * 2, m0 = tx * 2;
    float acc00 = 0.f, acc01 = 0.f, acc10 = 0.f, acc11 = 0.f;
    for (int jx = 0; jx < MLPH; jx++) {
        float w = sw2[jx], bb = sb1[jx];
        float a0 = Sh[h0][jx] + bb;
        float a1 = Sh[h0 + 1][jx] + bb;
        float c0 = Sm[m0][jx];
        float c1 = Sm[m0 + 1][jx];
        acc00 = fmaf(tanhap(a0 + c0), w, acc00);
        acc01 = fmaf(tanhap(a0 + c1), w, acc01);
        acc10 = fmaf(tanhap(a1 + c0), w, acc10);
        acc11 = fmaf(tanhap(a1 + c1), w, acc11);
    }
    float b2v = __ldg(b2);
    g_scores[(size_t)(bh + h0) * SEQ + bm + m0]         = acc00 + b2v;
    g_scores[(size_t)(bh + h0) * SEQ + bm + m0 + 1]     = acc01 + b2v;
    g_scores[(size_t)(bh + h0 + 1) * SEQ + bm + m0]     = acc10 + b2v;
    g_scores[(size_t)(bh + h0 + 1) * SEQ + bm + m0 + 1] = acc11 + b2v;
}

// ---------------- softmax over axis 0 ----------------
__global__ void softmax0(float* __restrict__ out) {
    int m = blockIdx.x;
    int tid = threadIdx.x;  // 128
    float v[4];
#pragma unroll
    for (int i = 0; i < 4; i++) v[i] = g_scores[(size_t)(tid + 128 * i) * SEQ + m];
    float mx = fmaxf(fmaxf(v[0], v[1]), fmaxf(v[2], v[3]));
    __shared__ float red[128];
    red[tid] = mx; __syncthreads();
    for (int o = 64; o > 0; o >>= 1) {
        if (tid < o) red[tid] = fmaxf(red[tid], red[tid + o]);
        __syncthreads();
    }
    mx = red[0]; __syncthreads();
    float e[4]; float ssum = 0.f;
#pragma unroll
    for (int i = 0; i < 4; i++) { e[i] = __expf(v[i] - mx); ssum += e[i]; }
    red[tid] = ssum; __syncthreads();
    for (int o = 64; o > 0; o >>= 1) {
        if (tid < o) red[tid] += red[tid + o];
        __syncthreads();
    }
    float inv = 1.f / red[0];
#pragma unroll
    for (int i = 0; i < 4; i++) out[(size_t)(tid + 128 * i) * SEQ + m] = e[i] * inv;
}

// ---------------- launch ----------------
extern "C" void kernel_launch(void* const* d_in, const int* in_sizes, int n_in,
                              void* d_out, int out_size) {
    const int*   wi  = (const int*)d_in[0];
    const int*   pi  = (const int*)d_in[1];
    const float* we  = (const float*)d_in[2];
    const float* pe  = (const float*)d_in[3];
    const float* wih0f = (const float*)d_in[4];
    const float* whh0f = (const float*)d_in[5];
    const float* b0f   = (const float*)d_in[6];
    const float* wih0b = (const float*)d_in[7];
    const float* whh0b = (const float*)d_in[8];
    const float* b0b   = (const float*)d_in[9];
    const float* wih1f = (const float*)d_in[10];
    const float* whh1f = (const float*)d_in[11];
    const float* b1f   = (const float*)d_in[12];
    const float* wih1b = (const float*)d_in[13];
    const float* whh1b = (const float*)d_in[14];
    const float* b1b   = (const float*)d_in[15];
    const float* W1    = (const float*)d_in[16];
    const float* b1    = (const float*)d_in[17];
    const float* W2    = (const float*)d_in[18];
    const float* b2    = (const float*)d_in[19];
    float* out = (float*)d_out;

    float *p_x0, *p_xw0, *p_xw1, *p_h0, *p_h1, *p_sh, *p_sm;
    cudaGetSymbolAddress((void**)&p_x0, g_x0);
    cudaGetSymbolAddress((void**)&p_xw0, g_xw0);
    cudaGetSymbolAddress((void**)&p_xw1, g_xw1);
    cudaGetSymbolAddress((void**)&p_h0, g_h0);
    cudaGetSymbolAddress((void**)&p_h1, g_h1);
    cudaGetSymbolAddress((void**)&p_sh, g_sh);
    cudaGetSymbolAddress((void**)&p_sm, g_sm);

    // 1. embeddings
    embed_kernel<<<SEQ, 256>>>(wi, pi, we, pe);

    // 2. layer0 input GEMMs (both directions in one launch, TF32 tensor cores)
    {
        dim3 grid(GATES / 64, SEQ / 128, 2);
        gemm_big<<<grid, 256>>>(p_x0, IN0, wih0f, wih0b, IN0, b0f, b0b,
                                p_xw0, p_xw1, GATES, SEQ, GATES, IN0);
    }

    // 3. layer0 recurrence
    lstm_layer<<<2 * RCTAS, 256>>>(whh0f, whh0b, p_xw0, p_xw1, p_h0);

    // 4. layer1 input GEMMs (both directions in one launch, TF32 tensor cores)
    {
        dim3 grid(GATES / 64, SEQ / 128, 2);
        gemm_big<<<grid, 256>>>(p_h0, IN1, wih1f, wih1b, IN1, b1f, b1b,
                                p_xw0, p_xw1, GATES, SEQ, GATES, IN1);
    }

    // 5. layer1 recurrence
    lstm_layer<<<2 * RCTAS, 256>>>(whh1f, whh1b, p_xw0, p_xw1, p_h1);

    // 6. MLP projections, both halves in one launch (W1 is [100, 2048] -> ldb = PAIRD)
    {
        dim3 grid((MLPH + 63) / 64, SEQ / 64, 2);
        gemm_dual<<<grid, 256>>>(p_h1, 2 * HID, W1, W1 + 1024, PAIRD, nullptr, nullptr,
                                 p_sh, p_sm, MLPH, SEQ, MLPH, 2 * HID);
    }

    // 7. pairwise scores
    {
        dim3 grid(SEQ / 32, SEQ / 32);
        pair_score<<<grid, 256>>>(b1, W2, b2);
    }

    // 8. softmax over heads (axis 0)
    softmax0<<<SEQ, 128>>>(out);
}